// round 1
// baseline (speedup 1.0000x reference)
#include <cuda_runtime.h>
#include <math.h>

// Problem constants
#define BB   8
#define CCH  256
#define HH   96
#define WW   96
#define HWN  (HH*WW)        // 9216
#define OC   256
#define KF   4

// Scratch (static __device__ arrays; no allocation anywhere)
__device__ float g_proj[(size_t)BB * HWN * OC];   // [b][p][o]  pixel-major, 75.5 MB
__device__ float g_wcT[CCH * OC];                 // WcT[c][o] = Wc[o][c]
__device__ int   g_sidx[BB * HWN * 16];           // per (b,p): 16 gather offsets (pre-scaled by OC)
__device__ float g_swt [BB * HWN * 16];           // per (b,p): 16 fused weights (softmax*bilinear*valid)

// ---------------------------------------------------------------------------
// packed f32x2 FMA (Blackwell): 2 fp32 FMAs per instruction
union P2 { float2 f; unsigned long long u; };
__device__ __forceinline__ void fma2(unsigned long long& d,
                                     unsigned long long a,
                                     unsigned long long b) {
    asm("fma.rn.f32x2 %0, %1, %2, %0;" : "+l"(d) : "l"(a), "l"(b));
}
__device__ __forceinline__ unsigned long long splat2(float a) {
    P2 t; t.f = make_float2(a, a); return t.u;
}
__device__ __forceinline__ unsigned long long pack2(float a, float b) {
    P2 t; t.f = make_float2(a, b); return t.u;
}

// ---------------------------------------------------------------------------
// Kernel 0: transpose Wc [OC][C] -> wcT [C][OC]   (tiny, 256KB)
__global__ void DFMAtt_transpose_wc(const float* __restrict__ Wc) {
    int o = blockIdx.x;
    int c = threadIdx.x;
    g_wcT[c * OC + o] = Wc[o * CCH + c];
}

// ---------------------------------------------------------------------------
// Kernel 1: proj[b][p][o] = sum_c x[b][c][p] * Wc[o][c] + bc[o]
// C = A * B : A[p][c] = x (col-major via stride HW), B[c][o] = wcT (row-major)
// 128x128 block tile, 8x8 per thread, f32x2 packed accumulation along o.
__global__ __launch_bounds__(256) void DFMAtt_gemm_proj(
        const float* __restrict__ x, const float* __restrict__ bc) {
    constexpr int BM = 128, BN = 128, BK = 16, TM = 8;
    __shared__ float As[BK][BM];
    __shared__ float Bs[BK][BN];

    int b  = blockIdx.z;
    int pm = blockIdx.x * BM;
    int on = blockIdx.y * BN;
    const float* A  = x + (size_t)b * CCH * HWN + pm;
    const float* Bt = g_wcT + on;

    int tid = threadIdx.x;
    int tx = tid & 15, ty = tid >> 4;
    int lr = tid >> 5;            // 0..7
    int lc = (tid & 31) * 4;      // 0..124

    unsigned long long acc[TM][4];
    #pragma unroll
    for (int i = 0; i < TM; i++)
        #pragma unroll
        for (int j = 0; j < 4; j++) acc[i][j] = 0ull;

    for (int k0 = 0; k0 < CCH; k0 += BK) {
        *(float4*)&As[lr    ][lc] = *(const float4*)&A[(size_t)(k0 + lr    ) * HWN + lc];
        *(float4*)&As[lr + 8][lc] = *(const float4*)&A[(size_t)(k0 + lr + 8) * HWN + lc];
        *(float4*)&Bs[lr    ][lc] = *(const float4*)&Bt[(k0 + lr    ) * OC + lc];
        *(float4*)&Bs[lr + 8][lc] = *(const float4*)&Bt[(k0 + lr + 8) * OC + lc];
        __syncthreads();
        #pragma unroll
        for (int k = 0; k < BK; k++) {
            float4 b0 = *(const float4*)&Bs[k][tx * 8];
            float4 b1 = *(const float4*)&Bs[k][tx * 8 + 4];
            unsigned long long b2[4];
            b2[0] = pack2(b0.x, b0.y);
            b2[1] = pack2(b0.z, b0.w);
            b2[2] = pack2(b1.x, b1.y);
            b2[3] = pack2(b1.z, b1.w);
            float4 a0 = *(const float4*)&As[k][ty * TM];
            float4 a1 = *(const float4*)&As[k][ty * TM + 4];
            float av[TM] = {a0.x, a0.y, a0.z, a0.w, a1.x, a1.y, a1.z, a1.w};
            #pragma unroll
            for (int i = 0; i < TM; i++) {
                unsigned long long a2 = splat2(av[i]);
                #pragma unroll
                for (int j = 0; j < 4; j++) fma2(acc[i][j], a2, b2[j]);
            }
        }
        __syncthreads();
    }

    // epilogue: add bias, store [p][o] contiguous in o
    float bias[8];
    #pragma unroll
    for (int j = 0; j < 8; j++) bias[j] = bc[on + tx * 8 + j];
    float* Cp = g_proj + ((size_t)b * HWN + pm + ty * TM) * OC + on + tx * 8;
    #pragma unroll
    for (int i = 0; i < TM; i++) {
        P2 t0, t1, t2, t3;
        t0.u = acc[i][0]; t1.u = acc[i][1]; t2.u = acc[i][2]; t3.u = acc[i][3];
        float4 v0 = make_float4(t0.f.x + bias[0], t0.f.y + bias[1],
                                t1.f.x + bias[2], t1.f.y + bias[3]);
        float4 v1 = make_float4(t2.f.x + bias[4], t2.f.y + bias[5],
                                t3.f.x + bias[6], t3.f.y + bias[7]);
        *(float4*)&Cp[(size_t)i * OC]     = v0;
        *(float4*)&Cp[(size_t)i * OC + 4] = v1;
    }
}

// ---------------------------------------------------------------------------
// Kernel 2: per pixel — 12 dots (4 flows x 2 comps + 4 logits), softmax,
// bilinear decomposition -> 16 (index, fused weight) pairs.
__global__ __launch_bounds__(128) void DFMAtt_flow(
        const float* __restrict__ x,
        const float* __restrict__ Woff, const float* __restrict__ boff,
        const float* __restrict__ Wwt,  const float* __restrict__ bwt) {
    __shared__ float sW[12][CCH];   // rows 0..7: Woff[k][j][:], rows 8..11: Wwt[k][:]
    int tid = threadIdx.x;
    for (int i = tid; i < 8 * CCH; i += 128) sW[i >> 8][i & 255] = Woff[i];
    for (int i = tid; i < 4 * CCH; i += 128) sW[8 + (i >> 8)][i & 255] = Wwt[i];
    __syncthreads();

    int b = blockIdx.y;
    int p = blockIdx.x * 128 + tid;
    const float* xp = x + (size_t)b * CCH * HWN + p;

    float acc[12];
    #pragma unroll
    for (int m = 0; m < 12; m++) acc[m] = 0.f;
    #pragma unroll 4
    for (int c = 0; c < CCH; c++) {
        float xv = xp[(size_t)c * HWN];
        #pragma unroll
        for (int m = 0; m < 12; m++) acc[m] = fmaf(xv, sW[m][c], acc[m]);
    }

    // softmax over k
    float lg[KF];
    #pragma unroll
    for (int k = 0; k < KF; k++) lg[k] = acc[8 + k] + bwt[k];
    float mx = fmaxf(fmaxf(lg[0], lg[1]), fmaxf(lg[2], lg[3]));
    float e[KF], s = 0.f;
    #pragma unroll
    for (int k = 0; k < KF; k++) { e[k] = expf(lg[k] - mx); s += e[k]; }
    float inv = 1.f / s;

    int px = p % WW, py = p / WW;
    int base = (b * HWN + p) * 16;
    #pragma unroll
    for (int k = 0; k < KF; k++) {
        float wk = e[k] * inv;
        float fx = acc[k * 2 + 0] + boff[k * 2 + 0];
        float fy = acc[k * 2 + 1] + boff[k * 2 + 1];
        // match reference op sequence exactly
        float vx = 2.0f * ((float)px + fx) / (float)(WW - 1) - 1.0f;
        float vy = 2.0f * ((float)py + fy) / (float)(HH - 1) - 1.0f;
        float ix = (vx + 1.0f) * ((float)WW * 0.5f) - 0.5f;
        float iy = (vy + 1.0f) * ((float)HH * 0.5f) - 0.5f;
        float x0f = floorf(ix), y0f = floorf(iy);
        float wx1 = ix - x0f, wx0 = 1.0f - wx1;
        float wy1 = iy - y0f, wy0 = 1.0f - wy1;
        int x0 = (int)x0f, y0 = (int)y0f;
        #pragma unroll
        for (int t = 0; t < 4; t++) {
            int xi = x0 + (t & 1);
            int yi = y0 + (t >> 1);
            float wt = ((t & 1) ? wx1 : wx0) * ((t >> 1) ? wy1 : wy0);
            bool valid = (xi >= 0) && (xi < WW) && (yi >= 0) && (yi < HH);
            int xc = min(max(xi, 0), WW - 1);
            int yc = min(max(yi, 0), HH - 1);
            g_sidx[base + k * 4 + t] = (yc * WW + xc) * OC;   // pre-scaled by channel stride
            g_swt [base + k * 4 + t] = valid ? (wk * wt) : 0.0f;
        }
    }
}

// ---------------------------------------------------------------------------
// Kernel 3: out[b][o][p] = sum_{i<16} w_i * proj[b][idx_i][o]
// Block = 32 pixels; gathers are contiguous 256-float columns (float4/lane),
// transpose through smem so the [b,o,h,w] store is coalesced.
__global__ __launch_bounds__(256) void DFMAtt_sample(float* __restrict__ out) {
    __shared__ float s_acc[32][257];   // [pixel][channel], pad for write-phase banks
    __shared__ int   s_idx[32][16];
    __shared__ float s_wt [32][16];

    int b  = blockIdx.y;
    int p0 = blockIdx.x * 32;
    int tid = threadIdx.x;

    {
        const int*   gi = g_sidx + (b * HWN + p0) * 16;
        const float* gw = g_swt  + (b * HWN + p0) * 16;
        for (int i = tid; i < 512; i += 256) {
            s_idx[i >> 4][i & 15] = gi[i];
            s_wt [i >> 4][i & 15] = gw[i];
        }
    }
    __syncthreads();

    const float* projb = g_proj + (size_t)b * HWN * OC;
    int lane = tid & 63;     // 64 lanes x float4 = 256 channels
    int psub = tid >> 6;     // 4 pixels in flight

    #pragma unroll 1
    for (int s = 0; s < 8; s++) {
        int pi = s * 4 + psub;
        const float* pb = projb + lane * 4;
        float ax = 0.f, ay = 0.f, az = 0.f, aw = 0.f;
        #pragma unroll
        for (int i = 0; i < 16; i++) {
            float wv = s_wt[pi][i];
            const float4 v = *(const float4*)(pb + s_idx[pi][i]);
            ax = fmaf(wv, v.x, ax);
            ay = fmaf(wv, v.y, ay);
            az = fmaf(wv, v.z, az);
            aw = fmaf(wv, v.w, aw);
        }
        float* sa = &s_acc[pi][lane * 4];
        sa[0] = ax; sa[1] = ay; sa[2] = az; sa[3] = aw;
    }
    __syncthreads();

    // coalesced write-out: 8 channels x 32 pixels per iteration
    float* ob = out + (size_t)b * OC * HWN + p0;
    int orow = tid >> 5;     // 0..7
    int pi   = tid & 31;
    #pragma unroll 1
    for (int j = 0; j < 32; j++) {
        int o = orow + j * 8;
        ob[(size_t)o * HWN + pi] = s_acc[pi][o];
    }
}

// ---------------------------------------------------------------------------
extern "C" void kernel_launch(void* const* d_in, const int* in_sizes, int n_in,
                              void* d_out, int out_size) {
    const float* x    = (const float*)d_in[0];
    const float* Wc   = (const float*)d_in[1];
    const float* bc   = (const float*)d_in[2];
    const float* Woff = (const float*)d_in[3];
    const float* boff = (const float*)d_in[4];
    const float* Wwt  = (const float*)d_in[5];
    const float* bwt  = (const float*)d_in[6];
    float* out = (float*)d_out;

    DFMAtt_transpose_wc<<<OC, CCH>>>(Wc);

    dim3 gg(HWN / 128, OC / 128, BB);
    DFMAtt_gemm_proj<<<gg, 256>>>(x, bc);

    dim3 gf(HWN / 128, BB);
    DFMAtt_flow<<<gf, 128>>>(x, Woff, boff, Wwt, bwt);

    dim3 gs(HWN / 32, BB);
    DFMAtt_sample<<<gs, 256>>>(out);
}

// round 3
// speedup vs baseline: 1.3331x; 1.3331x over previous
#include <cuda_runtime.h>
#include <cuda_bf16.h>
#include <math.h>
#include <stdint.h>

#define BB   8
#define CCH  256
#define HH   96
#define WW   96
#define HWN  (HH*WW)        // 9216
#define OC   256
#define KF   4

// Scratch
__device__ float g_proj[(size_t)BB * HWN * OC];          // [b][p][o] pixel-major
__device__ int   g_sidx[BB * HWN * 16];
__device__ float g_swt [BB * HWN * 16];
__device__ __nv_bfloat16 g_wb [2 * OC * CCH];            // [hi/lo][o][c]
__device__ __nv_bfloat16 g_xhi[(size_t)BB * CCH * HWN];  // [b][c][p]
__device__ __nv_bfloat16 g_xlo[(size_t)BB * CCH * HWN];

// ---------------------------------------------------------------------------
__device__ __forceinline__ uint32_t smem_u32(const void* p) {
    uint32_t a;
    asm("{ .reg .u64 t; cvta.to.shared.u64 t, %1; cvt.u32.u64 %0, t; }" : "=r"(a) : "l"(p));
    return a;
}
#define CPA16(dst, src) asm volatile("cp.async.cg.shared.global [%0], [%1], 16;" :: "r"(dst), "l"(src) : "memory")
#define CPA_COMMIT()    asm volatile("cp.async.commit_group;" ::: "memory")
#define CPA_WAIT1()     asm volatile("cp.async.wait_group 1;" ::: "memory")

#define LDSM_X4(r, a) \
    asm volatile("ldmatrix.sync.aligned.m8n8.x4.shared.b16 {%0,%1,%2,%3}, [%4];" \
        : "=r"((r)[0]), "=r"((r)[1]), "=r"((r)[2]), "=r"((r)[3]) : "r"(a))
#define LDSM_X4_T(r, a) \
    asm volatile("ldmatrix.sync.aligned.m8n8.x4.trans.shared.b16 {%0,%1,%2,%3}, [%4];" \
        : "=r"((r)[0]), "=r"((r)[1]), "=r"((r)[2]), "=r"((r)[3]) : "r"(a))

__device__ __forceinline__ void mma16816(float* c, const uint32_t* a, const uint32_t* b) {
    asm volatile("mma.sync.aligned.m16n8k16.row.col.f32.bf16.bf16.f32 "
                 "{%0,%1,%2,%3}, {%4,%5,%6,%7}, {%8,%9}, {%0,%1,%2,%3};"
                 : "+f"(c[0]), "+f"(c[1]), "+f"(c[2]), "+f"(c[3])
                 : "r"(a[0]), "r"(a[1]), "r"(a[2]), "r"(a[3]), "r"(b[0]), "r"(b[1]));
}

// ---------------------------------------------------------------------------
// Kernel 0: split Wc [o][c] into bf16 hi/lo row-major
__global__ void DFMAtt_wprep(const float* __restrict__ Wc) {
    int o = blockIdx.x, c = threadIdx.x;
    float w = Wc[o * CCH + c];
    __nv_bfloat16 hb = __float2bfloat16_rn(w);
    float hf = __bfloat162float(hb);
    g_wb[o * CCH + c]              = hb;
    g_wb[OC * CCH + o * CCH + c]   = __float2bfloat16_rn(w - hf);
}

// ---------------------------------------------------------------------------
// Kernel 1 (fused): per-pixel flows + softmax -> 16 (index, weight) pairs,
// AND bf16 hi/lo split of x written to g_xhi/g_xlo (same [b][c][p] layout).
__global__ __launch_bounds__(128) void DFMAtt_flow(
        const float* __restrict__ x,
        const float* __restrict__ Woff, const float* __restrict__ boff,
        const float* __restrict__ Wwt,  const float* __restrict__ bwt) {
    __shared__ float sW[12][CCH];
    int tid = threadIdx.x;
    for (int i = tid; i < 8 * CCH; i += 128) sW[i >> 8][i & 255] = Woff[i];
    for (int i = tid; i < 4 * CCH; i += 128) sW[8 + (i >> 8)][i & 255] = Wwt[i];
    __syncthreads();

    int b = blockIdx.y;
    int p = blockIdx.x * 128 + tid;
    const float* xp = x + (size_t)b * CCH * HWN + p;
    __nv_bfloat16* xh = g_xhi + (size_t)b * CCH * HWN + p;
    __nv_bfloat16* xl = g_xlo + (size_t)b * CCH * HWN + p;

    float acc[12];
    #pragma unroll
    for (int m = 0; m < 12; m++) acc[m] = 0.f;
    #pragma unroll 4
    for (int c = 0; c < CCH; c++) {
        float xv = xp[(size_t)c * HWN];
        __nv_bfloat16 hb = __float2bfloat16_rn(xv);
        float hf = __bfloat162float(hb);
        xh[(size_t)c * HWN] = hb;
        xl[(size_t)c * HWN] = __float2bfloat16_rn(xv - hf);
        #pragma unroll
        for (int m = 0; m < 12; m++) acc[m] = fmaf(xv, sW[m][c], acc[m]);
    }

    float lg[KF];
    #pragma unroll
    for (int k = 0; k < KF; k++) lg[k] = acc[8 + k] + bwt[k];
    float mx = fmaxf(fmaxf(lg[0], lg[1]), fmaxf(lg[2], lg[3]));
    float e[KF], ssum = 0.f;
    #pragma unroll
    for (int k = 0; k < KF; k++) { e[k] = expf(lg[k] - mx); ssum += e[k]; }
    float inv = 1.f / ssum;

    int px = p % WW, py = p / WW;
    int base = (b * HWN + p) * 16;
    #pragma unroll
    for (int k = 0; k < KF; k++) {
        float wk = e[k] * inv;
        float fx = acc[k * 2 + 0] + boff[k * 2 + 0];
        float fy = acc[k * 2 + 1] + boff[k * 2 + 1];
        float vx = 2.0f * ((float)px + fx) / (float)(WW - 1) - 1.0f;
        float vy = 2.0f * ((float)py + fy) / (float)(HH - 1) - 1.0f;
        float ix = (vx + 1.0f) * ((float)WW * 0.5f) - 0.5f;
        float iy = (vy + 1.0f) * ((float)HH * 0.5f) - 0.5f;
        float x0f = floorf(ix), y0f = floorf(iy);
        float wx1 = ix - x0f, wx0 = 1.0f - wx1;
        float wy1 = iy - y0f, wy0 = 1.0f - wy1;
        int x0 = (int)x0f, y0 = (int)y0f;
        #pragma unroll
        for (int t = 0; t < 4; t++) {
            int xi = x0 + (t & 1);
            int yi = y0 + (t >> 1);
            float wt = ((t & 1) ? wx1 : wx0) * ((t >> 1) ? wy1 : wy0);
            bool valid = (xi >= 0) && (xi < WW) && (yi >= 0) && (yi < HH);
            int xc = min(max(xi, 0), WW - 1);
            int yc = min(max(yi, 0), HH - 1);
            g_sidx[base + k * 4 + t] = (yc * WW + xc) * OC;
            g_swt [base + k * 4 + t] = valid ? (wk * wt) : 0.0f;
        }
    }
}

// ---------------------------------------------------------------------------
// Kernel 2: mma.sync bf16 3-pass GEMM.  proj[b][p][o] = x^T Wc^T + bc
// Persistent 148 CTAs: 74 per N-half; B half resident in smem; A streamed
// via cp.async double buffer. 128x128 tile, 8 warps of 64x32.
#define BS_STRIDE 264                       // bf16 elems per B row (528B)
#define AS_STRIDE 136                       // bf16 elems per A row (272B)
#define B_MAT_BYTES (128 * BS_STRIDE * 2)   // 67584
#define A_BUF_BYTES (32 * AS_STRIDE * 2)    // 8704
#define OFF_A (2 * B_MAT_BYTES)             // 135168
#define SMEM_TOT (OFF_A + 4 * A_BUF_BYTES)  // 169984

__device__ __forceinline__ void prefA(uint32_t smA, int s, int b, int ck, int prow, int tid) {
    #pragma unroll
    for (int it = 0; it < 4; it++) {
        int idx = tid + it * 256;
        int h = idx >> 9, rem = idx & 511;
        int r = rem >> 4, j = rem & 15;
        const __nv_bfloat16* src = (h ? g_xlo : g_xhi)
            + ((size_t)(b * CCH + ck * 32 + r)) * HWN + prow + j * 8;
        uint32_t dst = smA + (uint32_t)(s * 2 + h) * A_BUF_BYTES + r * (AS_STRIDE * 2) + j * 16;
        CPA16(dst, src);
    }
}

__global__ __launch_bounds__(256, 1) void DFMAtt_gemm_mma(const float* __restrict__ bc) {
    extern __shared__ unsigned char sm[];
    uint32_t sb = smem_u32(sm);
    int tid = threadIdx.x, wid = tid >> 5, lane = tid & 31;
    int nh = (blockIdx.x >= 74) ? 1 : 0;
    int local = blockIdx.x % 74;

    // Load resident B half: [hi/lo][128 o][256 c] with 528B padded rows
    {
        const __nv_bfloat16* wb = g_wb + (size_t)nh * 128 * CCH;
        for (int idx = tid; idx < 128 * 32 * 2; idx += 256) {
            int h = idx >> 12, rem = idx & 4095;
            int r = rem >> 5, j = rem & 31;
            const uint4* src = (const uint4*)(wb + (size_t)h * OC * CCH + r * CCH + j * 8);
            *(uint4*)(sm + h * B_MAT_BYTES + r * (BS_STRIDE * 2) + j * 16) = *src;
        }
    }
    __syncthreads();

    int wm = wid >> 2, wn = wid & 3;       // warp tile: 64 (m) x 32 (n)
    int p0w = wm * 64, o0w = wn * 32;
    int grp = lane >> 3, lr = lane & 7;

    // ldmatrix lane-address offsets
    int a_dc = ((grp >> 1) << 3) + lr;     // +8 rows for k8-15 groups
    int a_dp = (grp & 1) << 3;             // +8 pixels for m8-15 groups
    uint32_t aoff[4];
    #pragma unroll
    for (int i = 0; i < 4; i++)
        aoff[i] = (uint32_t)(a_dc * (AS_STRIDE * 2) + (p0w + i * 16 + a_dp) * 2);
    int b_dr = ((grp >> 1) << 3) + lr;     // +8 o rows
    int b_dk = (grp & 1) << 4;             // +16B for k8-15
    uint32_t boff[2];
    #pragma unroll
    for (int t = 0; t < 2; t++)
        boff[t] = (uint32_t)((o0w + t * 16 + b_dr) * (BS_STRIDE * 2) + b_dk);

    uint32_t smA = sb + OFF_A;

    // bias per lane (constant across tiles)
    int row = lane >> 2, col2 = (lane & 3) * 2;
    float2 biasv[4];
    #pragma unroll
    for (int nt = 0; nt < 4; nt++)
        biasv[nt] = *(const float2*)&bc[nh * 128 + o0w + nt * 8 + col2];

    for (int mt = local; mt < 576; mt += 74) {
        int b = mt / 72, prow = (mt % 72) * 128;

        float acc[4][4][4];
        #pragma unroll
        for (int i = 0; i < 4; i++)
            #pragma unroll
            for (int nt = 0; nt < 4; nt++)
                #pragma unroll
                for (int q = 0; q < 4; q++) acc[i][nt][q] = 0.f;

        prefA(smA, 0, b, 0, prow, tid); CPA_COMMIT();
        prefA(smA, 1, b, 1, prow, tid); CPA_COMMIT();

        #pragma unroll 1
        for (int ck = 0; ck < 8; ck++) {
            CPA_WAIT1();
            __syncthreads();
            int s = ck & 1;
            uint32_t Ah = smA + (uint32_t)(s * 2 + 0) * A_BUF_BYTES;
            uint32_t Al = smA + (uint32_t)(s * 2 + 1) * A_BUF_BYTES;

            #pragma unroll
            for (int ks = 0; ks < 2; ks++) {
                uint32_t ac = (uint32_t)(ks * 16 * (AS_STRIDE * 2));
                uint32_t bcf = (uint32_t)((ck * 32 + ks * 16) * 2);
                uint32_t ah[4][4], al[4][4];
                #pragma unroll
                for (int i = 0; i < 4; i++) {
                    LDSM_X4_T(ah[i], Ah + ac + aoff[i]);
                    LDSM_X4_T(al[i], Al + ac + aoff[i]);
                }
                uint32_t bh[2][4], bl[2][4];
                #pragma unroll
                for (int t = 0; t < 2; t++) {
                    LDSM_X4(bh[t], sb + bcf + boff[t]);
                    LDSM_X4(bl[t], sb + B_MAT_BYTES + bcf + boff[t]);
                }
                #pragma unroll
                for (int i = 0; i < 4; i++)
                    #pragma unroll
                    for (int nt = 0; nt < 4; nt++) {
                        const uint32_t* bH = &bh[nt >> 1][(nt & 1) * 2];
                        const uint32_t* bL = &bl[nt >> 1][(nt & 1) * 2];
                        mma16816(acc[i][nt], ah[i], bH);
                        mma16816(acc[i][nt], ah[i], bL);
                        mma16816(acc[i][nt], al[i], bH);
                    }
            }
            __syncthreads();
            if (ck + 2 < 8) prefA(smA, s, b, ck + 2, prow, tid);
            CPA_COMMIT();
        }

        // epilogue
        #pragma unroll
        for (int i = 0; i < 4; i++) {
            int p = prow + p0w + i * 16 + row;
            float* dst0 = g_proj + ((size_t)b * HWN + p) * OC + nh * 128 + o0w + col2;
            #pragma unroll
            for (int nt = 0; nt < 4; nt++) {
                float2 v0 = make_float2(acc[i][nt][0] + biasv[nt].x, acc[i][nt][1] + biasv[nt].y);
                float2 v1 = make_float2(acc[i][nt][2] + biasv[nt].x, acc[i][nt][3] + biasv[nt].y);
                *(float2*)(dst0 + nt * 8)            = v0;
                *(float2*)(dst0 + nt * 8 + 8 * OC)   = v1;
            }
        }
    }
}

// ---------------------------------------------------------------------------
// Kernel 3: out[b][o][p] = sum_{i<16} w_i * proj[b][idx_i][o]
__global__ __launch_bounds__(256) void DFMAtt_sample(float* __restrict__ out) {
    __shared__ float s_acc[32][257];
    __shared__ int   s_idx[32][16];
    __shared__ float s_wt [32][16];

    int b  = blockIdx.y;
    int p0 = blockIdx.x * 32;
    int tid = threadIdx.x;

    {
        const int*   gi = g_sidx + (b * HWN + p0) * 16;
        const float* gw = g_swt  + (b * HWN + p0) * 16;
        for (int i = tid; i < 512; i += 256) {
            s_idx[i >> 4][i & 15] = gi[i];
            s_wt [i >> 4][i & 15] = gw[i];
        }
    }
    __syncthreads();

    const float* projb = g_proj + (size_t)b * HWN * OC;
    int lane = tid & 63;
    int psub = tid >> 6;

    #pragma unroll 1
    for (int s = 0; s < 8; s++) {
        int pi = s * 4 + psub;
        const float* pb = projb + lane * 4;
        float ax = 0.f, ay = 0.f, az = 0.f, aw = 0.f;
        #pragma unroll
        for (int i = 0; i < 16; i++) {
            float wv = s_wt[pi][i];
            const float4 v = *(const float4*)(pb + s_idx[pi][i]);
            ax = fmaf(wv, v.x, ax);
            ay = fmaf(wv, v.y, ay);
            az = fmaf(wv, v.z, az);
            aw = fmaf(wv, v.w, aw);
        }
        float* sa = &s_acc[pi][lane * 4];
        sa[0] = ax; sa[1] = ay; sa[2] = az; sa[3] = aw;
    }
    __syncthreads();

    float* ob = out + (size_t)b * OC * HWN + p0;
    int orow = tid >> 5;
    int pi   = tid & 31;
    #pragma unroll 1
    for (int j = 0; j < 32; j++) {
        int o = orow + j * 8;
        ob[(size_t)o * HWN + pi] = s_acc[pi][o];
    }
}

// ---------------------------------------------------------------------------
extern "C" void kernel_launch(void* const* d_in, const int* in_sizes, int n_in,
                              void* d_out, int out_size) {
    const float* x    = (const float*)d_in[0];
    const float* Wc   = (const float*)d_in[1];
    const float* bc   = (const float*)d_in[2];
    const float* Woff = (const float*)d_in[3];
    const float* boff = (const float*)d_in[4];
    const float* Wwt  = (const float*)d_in[5];
    const float* bwt  = (const float*)d_in[6];
    float* out = (float*)d_out;

    cudaFuncSetAttribute(DFMAtt_gemm_mma,
                         cudaFuncAttributeMaxDynamicSharedMemorySize, SMEM_TOT);

    DFMAtt_wprep<<<OC, CCH>>>(Wc);

    dim3 gf(HWN / 128, BB);
    DFMAtt_flow<<<gf, 128>>>(x, Woff, boff, Wwt, bwt);

    DFMAtt_gemm_mma<<<148, 256, SMEM_TOT>>>(bc);

    dim3 gs(HWN / 32, BB);
    DFMAtt_sample<<<gs, 256>>>(out);
}

// round 4
// speedup vs baseline: 1.8879x; 1.4162x over previous
#include <cuda_runtime.h>
#include <cuda_fp16.h>
#include <math.h>
#include <stdint.h>

#define BB   8
#define CCH  256
#define HH   96
#define WW   96
#define HWN  (HH*WW)        // 9216
#define OC   256
#define KF   4

// Scratch
__device__ __half g_projh[(size_t)BB * HWN * OC];        // [b][p][o] pixel-major, fp16
__device__ int    g_sidx[BB * HWN * 16];
__device__ float  g_swt [BB * HWN * 16];
__device__ __half g_wh[OC * CCH];                        // fp16 hi of Wc [o][c]
__device__ __half g_wl[OC * CCH];                        // fp16 residual of Wc
__device__ __half g_xh[(size_t)BB * CCH * HWN];          // fp16(x) [b][c][p]

// ---------------------------------------------------------------------------
__device__ __forceinline__ uint32_t smem_u32(const void* p) {
    uint32_t a;
    asm("{ .reg .u64 t; cvta.to.shared.u64 t, %1; cvt.u32.u64 %0, t; }" : "=r"(a) : "l"(p));
    return a;
}
#define CPA16(dst, src) asm volatile("cp.async.cg.shared.global [%0], [%1], 16;" :: "r"(dst), "l"(src) : "memory")
#define CPA_COMMIT()    asm volatile("cp.async.commit_group;" ::: "memory")
#define CPA_WAIT1()     asm volatile("cp.async.wait_group 1;" ::: "memory")

#define LDSM_X4(r, a) \
    asm volatile("ldmatrix.sync.aligned.m8n8.x4.shared.b16 {%0,%1,%2,%3}, [%4];" \
        : "=r"((r)[0]), "=r"((r)[1]), "=r"((r)[2]), "=r"((r)[3]) : "r"(a))
#define LDSM_X4_T(r, a) \
    asm volatile("ldmatrix.sync.aligned.m8n8.x4.trans.shared.b16 {%0,%1,%2,%3}, [%4];" \
        : "=r"((r)[0]), "=r"((r)[1]), "=r"((r)[2]), "=r"((r)[3]) : "r"(a))

__device__ __forceinline__ void mma16816(float* c, const uint32_t* a, const uint32_t* b) {
    asm volatile("mma.sync.aligned.m16n8k16.row.col.f32.f16.f16.f32 "
                 "{%0,%1,%2,%3}, {%4,%5,%6,%7}, {%8,%9}, {%0,%1,%2,%3};"
                 : "+f"(c[0]), "+f"(c[1]), "+f"(c[2]), "+f"(c[3])
                 : "r"(a[0]), "r"(a[1]), "r"(a[2]), "r"(a[3]), "r"(b[0]), "r"(b[1]));
}

// ---------------------------------------------------------------------------
// Kernel 0: split Wc [o][c] into fp16 hi + fp16 residual
__global__ void DFMAtt_wprep(const float* __restrict__ Wc) {
    int o = blockIdx.x, c = threadIdx.x;
    float w = Wc[o * CCH + c];
    __half hh = __float2half_rn(w);
    g_wh[o * CCH + c] = hh;
    g_wl[o * CCH + c] = __float2half_rn(w - __half2float(hh));
}

// ---------------------------------------------------------------------------
// Kernel 1 (fused): per-pixel flows + softmax -> 16 (index, weight) pairs,
// AND fp16 conversion of x into g_xh (same [b][c][p] layout).
__global__ __launch_bounds__(128) void DFMAtt_flow(
        const float* __restrict__ x,
        const float* __restrict__ Woff, const float* __restrict__ boff,
        const float* __restrict__ Wwt,  const float* __restrict__ bwt) {
    __shared__ float sW[12][CCH];
    int tid = threadIdx.x;
    for (int i = tid; i < 8 * CCH; i += 128) sW[i >> 8][i & 255] = Woff[i];
    for (int i = tid; i < 4 * CCH; i += 128) sW[8 + (i >> 8)][i & 255] = Wwt[i];
    __syncthreads();

    int b = blockIdx.y;
    int p = blockIdx.x * 128 + tid;
    const float* xp = x + (size_t)b * CCH * HWN + p;
    __half* xh = g_xh + (size_t)b * CCH * HWN + p;

    float acc[12];
    #pragma unroll
    for (int m = 0; m < 12; m++) acc[m] = 0.f;
    #pragma unroll 4
    for (int c = 0; c < CCH; c++) {
        float xv = xp[(size_t)c * HWN];
        xh[(size_t)c * HWN] = __float2half_rn(xv);
        #pragma unroll
        for (int m = 0; m < 12; m++) acc[m] = fmaf(xv, sW[m][c], acc[m]);
    }

    float lg[KF];
    #pragma unroll
    for (int k = 0; k < KF; k++) lg[k] = acc[8 + k] + bwt[k];
    float mx = fmaxf(fmaxf(lg[0], lg[1]), fmaxf(lg[2], lg[3]));
    float e[KF], ssum = 0.f;
    #pragma unroll
    for (int k = 0; k < KF; k++) { e[k] = expf(lg[k] - mx); ssum += e[k]; }
    float inv = 1.f / ssum;

    int px = p % WW, py = p / WW;
    int base = (b * HWN + p) * 16;
    #pragma unroll
    for (int k = 0; k < KF; k++) {
        float wk = e[k] * inv;
        float fx = acc[k * 2 + 0] + boff[k * 2 + 0];
        float fy = acc[k * 2 + 1] + boff[k * 2 + 1];
        float vx = 2.0f * ((float)px + fx) / (float)(WW - 1) - 1.0f;
        float vy = 2.0f * ((float)py + fy) / (float)(HH - 1) - 1.0f;
        float ix = (vx + 1.0f) * ((float)WW * 0.5f) - 0.5f;
        float iy = (vy + 1.0f) * ((float)HH * 0.5f) - 0.5f;
        float x0f = floorf(ix), y0f = floorf(iy);
        float wx1 = ix - x0f, wx0 = 1.0f - wx1;
        float wy1 = iy - y0f, wy0 = 1.0f - wy1;
        int x0 = (int)x0f, y0 = (int)y0f;
        #pragma unroll
        for (int t = 0; t < 4; t++) {
            int xi = x0 + (t & 1);
            int yi = y0 + (t >> 1);
            float wt = ((t & 1) ? wx1 : wx0) * ((t >> 1) ? wy1 : wy0);
            bool valid = (xi >= 0) && (xi < WW) && (yi >= 0) && (yi < HH);
            int xc = min(max(xi, 0), WW - 1);
            int yc = min(max(yi, 0), HH - 1);
            g_sidx[base + k * 4 + t] = (yc * WW + xc) * OC;
            g_swt [base + k * 4 + t] = valid ? (wk * wt) : 0.0f;
        }
    }
}

// ---------------------------------------------------------------------------
// Kernel 2: mma.sync fp16 2-pass GEMM.  proj = xh*(Wh + Wl) + bc  (fp16 out)
// Persistent 148 CTAs: 74 per N-half; Wh+Wl half resident in smem; xh
// streamed via cp.async double buffer (BK=64). 128x128 tile, 8 warps 64x32.
#define BS_STRIDE 264                       // half elems per B row (528B)
#define AS_STRIDE 136                       // half elems per A row (272B)
#define B_MAT_BYTES (128 * BS_STRIDE * 2)   // 67584
#define A_STG_BYTES (64 * AS_STRIDE * 2)    // 17408
#define OFF_A (2 * B_MAT_BYTES)             // 135168
#define SMEM_TOT (OFF_A + 2 * A_STG_BYTES)  // 169984

__device__ __forceinline__ void prefA(uint32_t smA, int s, int b, int ck, int prow, int tid) {
    #pragma unroll
    for (int it = 0; it < 4; it++) {
        int idx = tid + it * 256;
        int r = idx >> 4, j = idx & 15;
        const __half* src = g_xh + ((size_t)(b * CCH + ck * 64 + r)) * HWN + prow + j * 8;
        uint32_t dst = smA + (uint32_t)s * A_STG_BYTES + r * (AS_STRIDE * 2) + j * 16;
        CPA16(dst, src);
    }
}

__global__ __launch_bounds__(256, 1) void DFMAtt_gemm_mma(const float* __restrict__ bc) {
    extern __shared__ unsigned char sm[];
    uint32_t sb = smem_u32(sm);
    int tid = threadIdx.x, wid = tid >> 5, lane = tid & 31;
    int nh = (blockIdx.x >= 74) ? 1 : 0;
    int local = blockIdx.x % 74;

    // Resident B half: [hi/lo][128 o][256 c], 528B padded rows
    {
        for (int idx = tid; idx < 128 * 32 * 2; idx += 256) {
            int h = idx >> 12, rem = idx & 4095;
            int r = rem >> 5, j = rem & 31;
            const __half* wsrc = (h ? g_wl : g_wh) + (size_t)(nh * 128 + r) * CCH + j * 8;
            *(uint4*)(sm + h * B_MAT_BYTES + r * (BS_STRIDE * 2) + j * 16) = *(const uint4*)wsrc;
        }
    }
    __syncthreads();

    int wm = wid >> 2, wn = wid & 3;       // warp tile: 64 (m) x 32 (n)
    int p0w = wm * 64, o0w = wn * 32;
    int grp = lane >> 3, lr = lane & 7;

    int a_dc = ((grp >> 1) << 3) + lr;
    int a_dp = (grp & 1) << 3;
    uint32_t aoff[4];
    #pragma unroll
    for (int i = 0; i < 4; i++)
        aoff[i] = (uint32_t)(a_dc * (AS_STRIDE * 2) + (p0w + i * 16 + a_dp) * 2);
    int b_dr = ((grp >> 1) << 3) + lr;
    int b_dk = (grp & 1) << 4;
    uint32_t boff[2];
    #pragma unroll
    for (int t = 0; t < 2; t++)
        boff[t] = (uint32_t)((o0w + t * 16 + b_dr) * (BS_STRIDE * 2) + b_dk);

    uint32_t smA = sb + OFF_A;

    int row = lane >> 2, col2 = (lane & 3) * 2;
    float2 biasv[4];
    #pragma unroll
    for (int nt = 0; nt < 4; nt++)
        biasv[nt] = *(const float2*)&bc[nh * 128 + o0w + nt * 8 + col2];

    for (int mt = local; mt < 576; mt += 74) {
        int b = mt / 72, prow = (mt % 72) * 128;

        float acc[4][4][4];
        #pragma unroll
        for (int i = 0; i < 4; i++)
            #pragma unroll
            for (int nt = 0; nt < 4; nt++)
                #pragma unroll
                for (int q = 0; q < 4; q++) acc[i][nt][q] = 0.f;

        prefA(smA, 0, b, 0, prow, tid); CPA_COMMIT();
        prefA(smA, 1, b, 1, prow, tid); CPA_COMMIT();

        #pragma unroll 1
        for (int ck = 0; ck < 4; ck++) {
            CPA_WAIT1();
            __syncthreads();
            int s = ck & 1;
            uint32_t Ab = smA + (uint32_t)s * A_STG_BYTES;

            #pragma unroll
            for (int ks = 0; ks < 4; ks++) {
                uint32_t ac  = (uint32_t)(ks * 16 * (AS_STRIDE * 2));
                uint32_t bcf = (uint32_t)((ck * 64 + ks * 16) * 2);
                uint32_t ah[4][4];
                #pragma unroll
                for (int i = 0; i < 4; i++) LDSM_X4_T(ah[i], Ab + ac + aoff[i]);
                uint32_t bh[2][4], bl[2][4];
                #pragma unroll
                for (int t = 0; t < 2; t++) {
                    LDSM_X4(bh[t], sb + bcf + boff[t]);
                    LDSM_X4(bl[t], sb + B_MAT_BYTES + bcf + boff[t]);
                }
                #pragma unroll
                for (int i = 0; i < 4; i++)
                    #pragma unroll
                    for (int nt = 0; nt < 4; nt++) {
                        mma16816(acc[i][nt], ah[i], &bh[nt >> 1][(nt & 1) * 2]);
                        mma16816(acc[i][nt], ah[i], &bl[nt >> 1][(nt & 1) * 2]);
                    }
            }
            __syncthreads();
            if (ck + 2 < 4) prefA(smA, s, b, ck + 2, prow, tid);
            CPA_COMMIT();
        }

        // epilogue: bias add in fp32, store fp16
        #pragma unroll
        for (int i = 0; i < 4; i++) {
            int p = prow + p0w + i * 16 + row;
            __half* dst0 = g_projh + ((size_t)b * HWN + p) * OC + nh * 128 + o0w + col2;
            #pragma unroll
            for (int nt = 0; nt < 4; nt++) {
                __half2 v0 = __floats2half2_rn(acc[i][nt][0] + biasv[nt].x,
                                               acc[i][nt][1] + biasv[nt].y);
                __half2 v1 = __floats2half2_rn(acc[i][nt][2] + biasv[nt].x,
                                               acc[i][nt][3] + biasv[nt].y);
                *(__half2*)(dst0 + nt * 8)          = v0;
                *(__half2*)(dst0 + nt * 8 + 8 * OC) = v1;
            }
        }
    }
}

// ---------------------------------------------------------------------------
// Kernel 3: out[b][o][p] = sum_{i<16} w_i * projh[b][idx_i][o]   (fp16 gather)
__global__ __launch_bounds__(256) void DFMAtt_sample(float* __restrict__ out) {
    __shared__ float s_acc[32][257];
    __shared__ int   s_idx[32][16];
    __shared__ float s_wt [32][16];

    int b  = blockIdx.y;
    int p0 = blockIdx.x * 32;
    int tid = threadIdx.x;

    {
        const int*   gi = g_sidx + (b * HWN + p0) * 16;
        const float* gw = g_swt  + (b * HWN + p0) * 16;
        for (int i = tid; i < 512; i += 256) {
            s_idx[i >> 4][i & 15] = gi[i];
            s_wt [i >> 4][i & 15] = gw[i];
        }
    }
    __syncthreads();

    const __half* projb = g_projh + (size_t)b * HWN * OC;
    int lane = tid & 63;
    int psub = tid >> 6;

    #pragma unroll 1
    for (int s = 0; s < 8; s++) {
        int pi = s * 4 + psub;
        const __half* pb = projb + lane * 4;
        float ax = 0.f, ay = 0.f, az = 0.f, aw = 0.f;
        #pragma unroll
        for (int i = 0; i < 16; i++) {
            float wv = s_wt[pi][i];
            uint2 raw = *(const uint2*)(pb + s_idx[pi][i]);
            float2 f01 = __half22float2(*(__half2*)&raw.x);
            float2 f23 = __half22float2(*(__half2*)&raw.y);
            ax = fmaf(wv, f01.x, ax);
            ay = fmaf(wv, f01.y, ay);
            az = fmaf(wv, f23.x, az);
            aw = fmaf(wv, f23.y, aw);
        }
        float* sa = &s_acc[pi][lane * 4];
        sa[0] = ax; sa[1] = ay; sa[2] = az; sa[3] = aw;
    }
    __syncthreads();

    float* ob = out + (size_t)b * OC * HWN + p0;
    int orow = tid >> 5;
    int pi   = tid & 31;
    #pragma unroll 1
    for (int j = 0; j < 32; j++) {
        int o = orow + j * 8;
        ob[(size_t)o * HWN + pi] = s_acc[pi][o];
    }
}

// ---------------------------------------------------------------------------
extern "C" void kernel_launch(void* const* d_in, const int* in_sizes, int n_in,
                              void* d_out, int out_size) {
    const float* x    = (const float*)d_in[0];
    const float* Wc   = (const float*)d_in[1];
    const float* bc   = (const float*)d_in[2];
    const float* Woff = (const float*)d_in[3];
    const float* boff = (const float*)d_in[4];
    const float* Wwt  = (const float*)d_in[5];
    const float* bwt  = (const float*)d_in[6];
    float* out = (float*)d_out;

    cudaFuncSetAttribute(DFMAtt_gemm_mma,
                         cudaFuncAttributeMaxDynamicSharedMemorySize, SMEM_TOT);

    DFMAtt_wprep<<<OC, CCH>>>(Wc);

    dim3 gf(HWN / 128, BB);
    DFMAtt_flow<<<gf, 128>>>(x, Woff, boff, Wwt, bwt);

    DFMAtt_gemm_mma<<<148, 256, SMEM_TOT>>>(bc);

    dim3 gs(HWN / 32, BB);
    DFMAtt_sample<<<gs, 256>>>(out);
}

// round 5
// speedup vs baseline: 1.9131x; 1.0133x over previous
#include <cuda_runtime.h>
#include <cuda_fp16.h>
#include <math.h>
#include <stdint.h>

#define BB   8
#define CCH  256
#define HH   96
#define WW   96
#define HWN  (HH*WW)        // 9216
#define OC   256
#define KF   4

// Scratch
__device__ __half g_projh[(size_t)BB * HWN * OC];        // [b][p][o] pixel-major, fp16
__device__ int    g_sidx[BB * HWN * 16];
__device__ float  g_swt [BB * HWN * 16];
__device__ __half g_wh[OC * CCH];                        // fp16(Wc) [o][c]
__device__ __half g_xh[(size_t)BB * CCH * HWN];          // fp16(x) [b][c][p]

// ---------------------------------------------------------------------------
__device__ __forceinline__ uint32_t smem_u32(const void* p) {
    uint32_t a;
    asm("{ .reg .u64 t; cvta.to.shared.u64 t, %1; cvt.u32.u64 %0, t; }" : "=r"(a) : "l"(p));
    return a;
}
#define CPA16(dst, src) asm volatile("cp.async.cg.shared.global [%0], [%1], 16;" :: "r"(dst), "l"(src) : "memory")
#define CPA_COMMIT()    asm volatile("cp.async.commit_group;" ::: "memory")
#define CPA_WAIT1()     asm volatile("cp.async.wait_group 1;" ::: "memory")

#define LDSM_X4(r, a) \
    asm volatile("ldmatrix.sync.aligned.m8n8.x4.shared.b16 {%0,%1,%2,%3}, [%4];" \
        : "=r"((r)[0]), "=r"((r)[1]), "=r"((r)[2]), "=r"((r)[3]) : "r"(a))
#define LDSM_X4_T(r, a) \
    asm volatile("ldmatrix.sync.aligned.m8n8.x4.trans.shared.b16 {%0,%1,%2,%3}, [%4];" \
        : "=r"((r)[0]), "=r"((r)[1]), "=r"((r)[2]), "=r"((r)[3]) : "r"(a))

__device__ __forceinline__ void mma16816(float* c, const uint32_t* a, const uint32_t* b) {
    asm volatile("mma.sync.aligned.m16n8k16.row.col.f32.f16.f16.f32 "
                 "{%0,%1,%2,%3}, {%4,%5,%6,%7}, {%8,%9}, {%0,%1,%2,%3};"
                 : "+f"(c[0]), "+f"(c[1]), "+f"(c[2]), "+f"(c[3])
                 : "r"(a[0]), "r"(a[1]), "r"(a[2]), "r"(a[3]), "r"(b[0]), "r"(b[1]));
}

// ---------------------------------------------------------------------------
// Kernel 0: Wc -> fp16
__global__ void DFMAtt_wprep(const float* __restrict__ Wc) {
    int i = blockIdx.x * 256 + threadIdx.x;
    g_wh[i] = __float2half_rn(Wc[i]);
}

// ---------------------------------------------------------------------------
// Kernel 1 (fused): per-pixel flows + softmax -> 16 (index, weight) pairs,
// AND fp16 conversion of x into g_xh.
__global__ __launch_bounds__(128) void DFMAtt_flow(
        const float* __restrict__ x,
        const float* __restrict__ Woff, const float* __restrict__ boff,
        const float* __restrict__ Wwt,  const float* __restrict__ bwt) {
    __shared__ float sW[12][CCH];
    int tid = threadIdx.x;
    for (int i = tid; i < 8 * CCH; i += 128) sW[i >> 8][i & 255] = Woff[i];
    for (int i = tid; i < 4 * CCH; i += 128) sW[8 + (i >> 8)][i & 255] = Wwt[i];
    __syncthreads();

    int b = blockIdx.y;
    int p = blockIdx.x * 128 + tid;
    const float* xp = x + (size_t)b * CCH * HWN + p;
    __half* xh = g_xh + (size_t)b * CCH * HWN + p;

    float acc[12];
    #pragma unroll
    for (int m = 0; m < 12; m++) acc[m] = 0.f;
    #pragma unroll 4
    for (int c = 0; c < CCH; c++) {
        float xv = xp[(size_t)c * HWN];
        xh[(size_t)c * HWN] = __float2half_rn(xv);
        #pragma unroll
        for (int m = 0; m < 12; m++) acc[m] = fmaf(xv, sW[m][c], acc[m]);
    }

    float lg[KF];
    #pragma unroll
    for (int k = 0; k < KF; k++) lg[k] = acc[8 + k] + bwt[k];
    float mx = fmaxf(fmaxf(lg[0], lg[1]), fmaxf(lg[2], lg[3]));
    float e[KF], ssum = 0.f;
    #pragma unroll
    for (int k = 0; k < KF; k++) { e[k] = expf(lg[k] - mx); ssum += e[k]; }
    float inv = 1.f / ssum;

    int px = p % WW, py = p / WW;
    int base = (b * HWN + p) * 16;
    #pragma unroll
    for (int k = 0; k < KF; k++) {
        float wk = e[k] * inv;
        float fx = acc[k * 2 + 0] + boff[k * 2 + 0];
        float fy = acc[k * 2 + 1] + boff[k * 2 + 1];
        float vx = 2.0f * ((float)px + fx) / (float)(WW - 1) - 1.0f;
        float vy = 2.0f * ((float)py + fy) / (float)(HH - 1) - 1.0f;
        float ix = (vx + 1.0f) * ((float)WW * 0.5f) - 0.5f;
        float iy = (vy + 1.0f) * ((float)HH * 0.5f) - 0.5f;
        float x0f = floorf(ix), y0f = floorf(iy);
        float wx1 = ix - x0f, wx0 = 1.0f - wx1;
        float wy1 = iy - y0f, wy0 = 1.0f - wy1;
        int x0 = (int)x0f, y0 = (int)y0f;
        #pragma unroll
        for (int t = 0; t < 4; t++) {
            int xi = x0 + (t & 1);
            int yi = y0 + (t >> 1);
            float wt = ((t & 1) ? wx1 : wx0) * ((t >> 1) ? wy1 : wy0);
            bool valid = (xi >= 0) && (xi < WW) && (yi >= 0) && (yi < HH);
            int xc = min(max(xi, 0), WW - 1);
            int yc = min(max(yi, 0), HH - 1);
            g_sidx[base + k * 4 + t] = (yc * WW + xc) * OC;
            g_swt [base + k * 4 + t] = valid ? (wk * wt) : 0.0f;
        }
    }
}

// ---------------------------------------------------------------------------
// Kernel 2: mma.sync fp16 single-pass GEMM. proj = fp16(x)*fp16(Wc) + bc.
// Persistent 296 CTAs (2/SM): 148 per N-half; W half resident (66KB);
// xh streamed via cp.async double buffer (BK=32). 128x128 tile, 8 warps 64x32.
#define BS_STRIDE 264                       // half elems per B row (528B)
#define AS_STRIDE 136                       // half elems per A row (272B)
#define B_MAT_BYTES (128 * BS_STRIDE * 2)   // 67584
#define A_STG_BYTES (32 * AS_STRIDE * 2)    // 8704
#define OFF_A B_MAT_BYTES
#define SMEM_TOT (OFF_A + 2 * A_STG_BYTES)  // 84992  -> 2 CTAs/SM

__device__ __forceinline__ void prefA(uint32_t smA, int s, int b, int ck, int prow, int tid) {
    #pragma unroll
    for (int it = 0; it < 2; it++) {
        int idx = tid + it * 256;
        int r = idx >> 4, j = idx & 15;
        const __half* src = g_xh + ((size_t)(b * CCH + ck * 32 + r)) * HWN + prow + j * 8;
        uint32_t dst = smA + (uint32_t)s * A_STG_BYTES + r * (AS_STRIDE * 2) + j * 16;
        CPA16(dst, src);
    }
}

__global__ __launch_bounds__(256, 2) void DFMAtt_gemm_mma(const float* __restrict__ bc) {
    extern __shared__ unsigned char sm[];
    uint32_t sb = smem_u32(sm);
    int tid = threadIdx.x, wid = tid >> 5, lane = tid & 31;
    int nh = (blockIdx.x >= 148) ? 1 : 0;
    int local = blockIdx.x % 148;

    // Resident B half: [128 o][256 c], 528B padded rows
    for (int idx = tid; idx < 128 * 32; idx += 256) {
        int r = idx >> 5, j = idx & 31;
        const __half* wsrc = g_wh + (size_t)(nh * 128 + r) * CCH + j * 8;
        *(uint4*)(sm + r * (BS_STRIDE * 2) + j * 16) = *(const uint4*)wsrc;
    }
    __syncthreads();

    int wm = wid >> 2, wn = wid & 3;       // warp tile: 64 (m) x 32 (n)
    int p0w = wm * 64, o0w = wn * 32;
    int grp = lane >> 3, lr = lane & 7;

    int a_dc = ((grp >> 1) << 3) + lr;
    int a_dp = (grp & 1) << 3;
    uint32_t aoff[4];
    #pragma unroll
    for (int i = 0; i < 4; i++)
        aoff[i] = (uint32_t)(a_dc * (AS_STRIDE * 2) + (p0w + i * 16 + a_dp) * 2);
    int b_dr = ((grp >> 1) << 3) + lr;
    int b_dk = (grp & 1) << 4;
    uint32_t boff[2];
    #pragma unroll
    for (int t = 0; t < 2; t++)
        boff[t] = (uint32_t)((o0w + t * 16 + b_dr) * (BS_STRIDE * 2) + b_dk);

    uint32_t smA = sb + OFF_A;

    int row = lane >> 2, col2 = (lane & 3) * 2;
    float2 biasv[4];
    #pragma unroll
    for (int nt = 0; nt < 4; nt++)
        biasv[nt] = *(const float2*)&bc[nh * 128 + o0w + nt * 8 + col2];

    for (int mt = local; mt < 576; mt += 148) {
        int b = mt / 72, prow = (mt % 72) * 128;

        float acc[4][4][4];
        #pragma unroll
        for (int i = 0; i < 4; i++)
            #pragma unroll
            for (int nt = 0; nt < 4; nt++)
                #pragma unroll
                for (int q = 0; q < 4; q++) acc[i][nt][q] = 0.f;

        prefA(smA, 0, b, 0, prow, tid); CPA_COMMIT();
        prefA(smA, 1, b, 1, prow, tid); CPA_COMMIT();

        #pragma unroll 1
        for (int ck = 0; ck < 8; ck++) {
            CPA_WAIT1();
            __syncthreads();
            int s = ck & 1;
            uint32_t Ab = smA + (uint32_t)s * A_STG_BYTES;

            #pragma unroll
            for (int ks = 0; ks < 2; ks++) {
                uint32_t ac  = (uint32_t)(ks * 16 * (AS_STRIDE * 2));
                uint32_t bcf = (uint32_t)((ck * 32 + ks * 16) * 2);
                uint32_t ah[4][4];
                #pragma unroll
                for (int i = 0; i < 4; i++) LDSM_X4_T(ah[i], Ab + ac + aoff[i]);
                uint32_t bh[2][4];
                #pragma unroll
                for (int t = 0; t < 2; t++) LDSM_X4(bh[t], sb + bcf + boff[t]);
                #pragma unroll
                for (int i = 0; i < 4; i++)
                    #pragma unroll
                    for (int nt = 0; nt < 4; nt++)
                        mma16816(acc[i][nt], ah[i], &bh[nt >> 1][(nt & 1) * 2]);
            }
            __syncthreads();
            if (ck + 2 < 8) prefA(smA, s, b, ck + 2, prow, tid);
            CPA_COMMIT();
        }

        // epilogue: bias in fp32, store fp16
        #pragma unroll
        for (int i = 0; i < 4; i++) {
            int p = prow + p0w + i * 16 + row;
            __half* dst0 = g_projh + ((size_t)b * HWN + p) * OC + nh * 128 + o0w + col2;
            #pragma unroll
            for (int nt = 0; nt < 4; nt++) {
                __half2 v0 = __floats2half2_rn(acc[i][nt][0] + biasv[nt].x,
                                               acc[i][nt][1] + biasv[nt].y);
                __half2 v1 = __floats2half2_rn(acc[i][nt][2] + biasv[nt].x,
                                               acc[i][nt][3] + biasv[nt].y);
                *(__half2*)(dst0 + nt * 8)          = v0;
                *(__half2*)(dst0 + nt * 8 + 8 * OC) = v1;
            }
        }
    }
}

// ---------------------------------------------------------------------------
// Kernel 3: out[b][o][p] = sum_{i<16} w_i * projh[b][idx_i][o]
// 32 lanes/pixel, uint4 (8 halves) per lane; 8 pixels in flight.
__global__ __launch_bounds__(256) void DFMAtt_sample(float* __restrict__ out) {
    __shared__ float s_acc[32][257];
    __shared__ int   s_idx[32][16];
    __shared__ float s_wt [32][16];

    int b  = blockIdx.y;
    int p0 = blockIdx.x * 32;
    int tid = threadIdx.x;

    {
        const int*   gi = g_sidx + (b * HWN + p0) * 16;
        const float* gw = g_swt  + (b * HWN + p0) * 16;
        for (int i = tid; i < 512; i += 256) {
            s_idx[i >> 4][i & 15] = gi[i];
            s_wt [i >> 4][i & 15] = gw[i];
        }
    }
    __syncthreads();

    const __half* projb = g_projh + (size_t)b * HWN * OC;
    int lane = tid & 31;            // 32 lanes x 8 halves = 256 channels
    int pg   = tid >> 5;            // 8 pixels in flight

    #pragma unroll 1
    for (int s = 0; s < 4; s++) {
        int pi = s * 8 + pg;        // uniform within warp
        const __half* pb = projb + lane * 8;
        float f0 = 0.f, f1 = 0.f, f2 = 0.f, f3 = 0.f;
        float f4 = 0.f, f5 = 0.f, f6 = 0.f, f7 = 0.f;
        #pragma unroll
        for (int i = 0; i < 16; i++) {
            float wv = s_wt[pi][i];
            if (wv != 0.f) {        // warp-uniform branch
                uint4 raw = *(const uint4*)(pb + s_idx[pi][i]);
                float2 a0 = __half22float2(*(__half2*)&raw.x);
                float2 a1 = __half22float2(*(__half2*)&raw.y);
                float2 a2 = __half22float2(*(__half2*)&raw.z);
                float2 a3 = __half22float2(*(__half2*)&raw.w);
                f0 = fmaf(wv, a0.x, f0); f1 = fmaf(wv, a0.y, f1);
                f2 = fmaf(wv, a1.x, f2); f3 = fmaf(wv, a1.y, f3);
                f4 = fmaf(wv, a2.x, f4); f5 = fmaf(wv, a2.y, f5);
                f6 = fmaf(wv, a3.x, f6); f7 = fmaf(wv, a3.y, f7);
            }
        }
        float* sa = &s_acc[pi][lane * 8];
        sa[0] = f0; sa[1] = f1; sa[2] = f2; sa[3] = f3;
        sa[4] = f4; sa[5] = f5; sa[6] = f6; sa[7] = f7;
    }
    __syncthreads();

    float* ob = out + (size_t)b * OC * HWN + p0;
    int orow = tid >> 5;
    int pi   = tid & 31;
    #pragma unroll 1
    for (int j = 0; j < 32; j++) {
        int o = orow + j * 8;
        ob[(size_t)o * HWN + pi] = s_acc[pi][o];
    }
}

// ---------------------------------------------------------------------------
extern "C" void kernel_launch(void* const* d_in, const int* in_sizes, int n_in,
                              void* d_out, int out_size) {
    const float* x    = (const float*)d_in[0];
    const float* Wc   = (const float*)d_in[1];
    const float* bc   = (const float*)d_in[2];
    const float* Woff = (const float*)d_in[3];
    const float* boff = (const float*)d_in[4];
    const float* Wwt  = (const float*)d_in[5];
    const float* bwt  = (const float*)d_in[6];
    float* out = (float*)d_out;

    cudaFuncSetAttribute(DFMAtt_gemm_mma,
                         cudaFuncAttributeMaxDynamicSharedMemorySize, SMEM_TOT);

    DFMAtt_wprep<<<OC, 256>>>(Wc);

    dim3 gf(HWN / 128, BB);
    DFMAtt_flow<<<gf, 128>>>(x, Woff, boff, Wwt, bwt);

    DFMAtt_gemm_mma<<<296, 256, SMEM_TOT>>>(bc);

    dim3 gs(HWN / 32, BB);
    DFMAtt_sample<<<gs, 256>>>(out);
}

// round 6
// speedup vs baseline: 2.2208x; 1.1609x over previous
#include <cuda_runtime.h>
#include <cuda_fp16.h>
#include <math.h>
#include <stdint.h>

#define BB   8
#define CCH  256
#define HH   96
#define WW   96
#define HWN  (HH*WW)        // 9216
#define OC   256
#define KF   4

// Scratch
__device__ __half g_projh[(size_t)BB * HWN * OC];        // [b][p][o] pixel-major, fp16
__device__ int    g_sidx[BB * HWN * 16];                 // compacted gather offsets
__device__ float  g_swt [BB * HWN * 16];                 // compacted fused weights
__device__ int    g_scnt[BB * HWN];                      // per-pixel tap count (even)
__device__ __half g_wh[OC * CCH];                        // fp16(Wc) [o][c]
__device__ __half g_xh[(size_t)BB * CCH * HWN];          // fp16(x) [b][c][p]

// ---------------------------------------------------------------------------
__device__ __forceinline__ uint32_t smem_u32(const void* p) {
    uint32_t a;
    asm("{ .reg .u64 t; cvta.to.shared.u64 t, %1; cvt.u32.u64 %0, t; }" : "=r"(a) : "l"(p));
    return a;
}
#define CPA16(dst, src) asm volatile("cp.async.cg.shared.global [%0], [%1], 16;" :: "r"(dst), "l"(src) : "memory")
#define CPA_COMMIT()    asm volatile("cp.async.commit_group;" ::: "memory")
#define CPA_WAIT1()     asm volatile("cp.async.wait_group 1;" ::: "memory")

#define LDSM_X4(r, a) \
    asm volatile("ldmatrix.sync.aligned.m8n8.x4.shared.b16 {%0,%1,%2,%3}, [%4];" \
        : "=r"((r)[0]), "=r"((r)[1]), "=r"((r)[2]), "=r"((r)[3]) : "r"(a))
#define LDSM_X4_T(r, a) \
    asm volatile("ldmatrix.sync.aligned.m8n8.x4.trans.shared.b16 {%0,%1,%2,%3}, [%4];" \
        : "=r"((r)[0]), "=r"((r)[1]), "=r"((r)[2]), "=r"((r)[3]) : "r"(a))

__device__ __forceinline__ void mma16816(float* c, const uint32_t* a, const uint32_t* b) {
    asm volatile("mma.sync.aligned.m16n8k16.row.col.f32.f16.f16.f32 "
                 "{%0,%1,%2,%3}, {%4,%5,%6,%7}, {%8,%9}, {%0,%1,%2,%3};"
                 : "+f"(c[0]), "+f"(c[1]), "+f"(c[2]), "+f"(c[3])
                 : "r"(a[0]), "r"(a[1]), "r"(a[2]), "r"(a[3]), "r"(b[0]), "r"(b[1]));
}

// ---------------------------------------------------------------------------
// Kernel 0: Wc -> fp16
__global__ void DFMAtt_wprep(const float* __restrict__ Wc) {
    int i = blockIdx.x * 256 + threadIdx.x;
    g_wh[i] = __float2half_rn(Wc[i]);
}

// ---------------------------------------------------------------------------
// Kernel 1 (fused): flows + softmax -> dedupe -> compacted (idx, wt, cnt),
// AND fp16 conversion of x into g_xh.
__global__ __launch_bounds__(128) void DFMAtt_flow(
        const float* __restrict__ x,
        const float* __restrict__ Woff, const float* __restrict__ boff,
        const float* __restrict__ Wwt,  const float* __restrict__ bwt) {
    __shared__ float sW[12][CCH];
    int tid = threadIdx.x;
    for (int i = tid; i < 8 * CCH; i += 128) sW[i >> 8][i & 255] = Woff[i];
    for (int i = tid; i < 4 * CCH; i += 128) sW[8 + (i >> 8)][i & 255] = Wwt[i];
    __syncthreads();

    int b = blockIdx.y;
    int p = blockIdx.x * 128 + tid;
    const float* xp = x + (size_t)b * CCH * HWN + p;
    __half* xh = g_xh + (size_t)b * CCH * HWN + p;

    float acc[12];
    #pragma unroll
    for (int m = 0; m < 12; m++) acc[m] = 0.f;
    #pragma unroll 4
    for (int c = 0; c < CCH; c++) {
        float xv = xp[(size_t)c * HWN];
        xh[(size_t)c * HWN] = __float2half_rn(xv);
        #pragma unroll
        for (int m = 0; m < 12; m++) acc[m] = fmaf(xv, sW[m][c], acc[m]);
    }

    float lg[KF];
    #pragma unroll
    for (int k = 0; k < KF; k++) lg[k] = acc[8 + k] + bwt[k];
    float mx = fmaxf(fmaxf(lg[0], lg[1]), fmaxf(lg[2], lg[3]));
    float e[KF], ssum = 0.f;
    #pragma unroll
    for (int k = 0; k < KF; k++) { e[k] = expf(lg[k] - mx); ssum += e[k]; }
    float inv = 1.f / ssum;

    int px = p % WW, py = p / WW;

    int   idxr[16];
    float wtr [16];
    bool  keep[16];
    #pragma unroll
    for (int k = 0; k < KF; k++) {
        float wk = e[k] * inv;
        float fx = acc[k * 2 + 0] + boff[k * 2 + 0];
        float fy = acc[k * 2 + 1] + boff[k * 2 + 1];
        float vx = 2.0f * ((float)px + fx) / (float)(WW - 1) - 1.0f;
        float vy = 2.0f * ((float)py + fy) / (float)(HH - 1) - 1.0f;
        float ix = (vx + 1.0f) * ((float)WW * 0.5f) - 0.5f;
        float iy = (vy + 1.0f) * ((float)HH * 0.5f) - 0.5f;
        float x0f = floorf(ix), y0f = floorf(iy);
        float wx1 = ix - x0f, wx0 = 1.0f - wx1;
        float wy1 = iy - y0f, wy0 = 1.0f - wy1;
        int x0 = (int)x0f, y0 = (int)y0f;
        #pragma unroll
        for (int t = 0; t < 4; t++) {
            int xi = x0 + (t & 1);
            int yi = y0 + (t >> 1);
            float wt = ((t & 1) ? wx1 : wx0) * ((t >> 1) ? wy1 : wy0);
            bool valid = (xi >= 0) && (xi < WW) && (yi >= 0) && (yi < HH);
            int xc = min(max(xi, 0), WW - 1);
            int yc = min(max(yi, 0), HH - 1);
            int q = k * 4 + t;
            idxr[q] = (yc * WW + xc) * OC;
            wtr [q] = valid ? (wk * wt) : 0.0f;
            keep[q] = true;
        }
    }

    // exact dedupe: merge weights of identical indices (register-resident)
    #pragma unroll
    for (int j = 1; j < 16; j++)
        #pragma unroll
        for (int i = 0; i < j; i++)
            if (keep[j] && keep[i] && idxr[j] == idxr[i]) {
                wtr[i] += wtr[j];
                keep[j] = false;
            }

    int base = (b * HWN + p) * 16;
    int cnt = 0;
    #pragma unroll
    for (int t = 0; t < 16; t++)
        if (keep[t] && wtr[t] != 0.0f) {
            g_sidx[base + cnt] = idxr[t];
            g_swt [base + cnt] = wtr[t];
            cnt++;
        }
    if (cnt & 1) {                         // pad to even for unroll-2 gather
        g_sidx[base + cnt] = 0;
        g_swt [base + cnt] = 0.0f;
        cnt++;
    }
    g_scnt[b * HWN + p] = cnt;
}

// ---------------------------------------------------------------------------
// Kernel 2: mma.sync fp16 single-pass GEMM. proj = fp16(x)*fp16(Wc) + bc.
// Persistent 296 CTAs (2/SM): 148 per N-half; W half resident (66KB);
// xh streamed via cp.async double buffer (BK=32). 128x128 tile, 8 warps 64x32.
#define BS_STRIDE 264
#define AS_STRIDE 136
#define B_MAT_BYTES (128 * BS_STRIDE * 2)   // 67584
#define A_STG_BYTES (32 * AS_STRIDE * 2)    // 8704
#define OFF_A B_MAT_BYTES
#define SMEM_TOT (OFF_A + 2 * A_STG_BYTES)  // 84992  -> 2 CTAs/SM

__device__ __forceinline__ void prefA(uint32_t smA, int s, int b, int ck, int prow, int tid) {
    #pragma unroll
    for (int it = 0; it < 2; it++) {
        int idx = tid + it * 256;
        int r = idx >> 4, j = idx & 15;
        const __half* src = g_xh + ((size_t)(b * CCH + ck * 32 + r)) * HWN + prow + j * 8;
        uint32_t dst = smA + (uint32_t)s * A_STG_BYTES + r * (AS_STRIDE * 2) + j * 16;
        CPA16(dst, src);
    }
}

__global__ __launch_bounds__(256, 2) void DFMAtt_gemm_mma(const float* __restrict__ bc) {
    extern __shared__ unsigned char sm[];
    uint32_t sb = smem_u32(sm);
    int tid = threadIdx.x, wid = tid >> 5, lane = tid & 31;
    int nh = (blockIdx.x >= 148) ? 1 : 0;
    int local = blockIdx.x % 148;

    for (int idx = tid; idx < 128 * 32; idx += 256) {
        int r = idx >> 5, j = idx & 31;
        const __half* wsrc = g_wh + (size_t)(nh * 128 + r) * CCH + j * 8;
        *(uint4*)(sm + r * (BS_STRIDE * 2) + j * 16) = *(const uint4*)wsrc;
    }
    __syncthreads();

    int wm = wid >> 2, wn = wid & 3;
    int p0w = wm * 64, o0w = wn * 32;
    int grp = lane >> 3, lr = lane & 7;

    int a_dc = ((grp >> 1) << 3) + lr;
    int a_dp = (grp & 1) << 3;
    uint32_t aoff[4];
    #pragma unroll
    for (int i = 0; i < 4; i++)
        aoff[i] = (uint32_t)(a_dc * (AS_STRIDE * 2) + (p0w + i * 16 + a_dp) * 2);
    int b_dr = ((grp >> 1) << 3) + lr;
    int b_dk = (grp & 1) << 4;
    uint32_t boff[2];
    #pragma unroll
    for (int t = 0; t < 2; t++)
        boff[t] = (uint32_t)((o0w + t * 16 + b_dr) * (BS_STRIDE * 2) + b_dk);

    uint32_t smA = sb + OFF_A;

    int row = lane >> 2, col2 = (lane & 3) * 2;
    float2 biasv[4];
    #pragma unroll
    for (int nt = 0; nt < 4; nt++)
        biasv[nt] = *(const float2*)&bc[nh * 128 + o0w + nt * 8 + col2];

    for (int mt = local; mt < 576; mt += 148) {
        int b = mt / 72, prow = (mt % 72) * 128;

        float acc[4][4][4];
        #pragma unroll
        for (int i = 0; i < 4; i++)
            #pragma unroll
            for (int nt = 0; nt < 4; nt++)
                #pragma unroll
                for (int q = 0; q < 4; q++) acc[i][nt][q] = 0.f;

        prefA(smA, 0, b, 0, prow, tid); CPA_COMMIT();
        prefA(smA, 1, b, 1, prow, tid); CPA_COMMIT();

        #pragma unroll 1
        for (int ck = 0; ck < 8; ck++) {
            CPA_WAIT1();
            __syncthreads();
            int s = ck & 1;
            uint32_t Ab = smA + (uint32_t)s * A_STG_BYTES;

            #pragma unroll
            for (int ks = 0; ks < 2; ks++) {
                uint32_t ac  = (uint32_t)(ks * 16 * (AS_STRIDE * 2));
                uint32_t bcf = (uint32_t)((ck * 32 + ks * 16) * 2);
                uint32_t ah[4][4];
                #pragma unroll
                for (int i = 0; i < 4; i++) LDSM_X4_T(ah[i], Ab + ac + aoff[i]);
                uint32_t bh[2][4];
                #pragma unroll
                for (int t = 0; t < 2; t++) LDSM_X4(bh[t], sb + bcf + boff[t]);
                #pragma unroll
                for (int i = 0; i < 4; i++)
                    #pragma unroll
                    for (int nt = 0; nt < 4; nt++)
                        mma16816(acc[i][nt], ah[i], &bh[nt >> 1][(nt & 1) * 2]);
            }
            __syncthreads();
            if (ck + 2 < 8) prefA(smA, s, b, ck + 2, prow, tid);
            CPA_COMMIT();
        }

        #pragma unroll
        for (int i = 0; i < 4; i++) {
            int p = prow + p0w + i * 16 + row;
            __half* dst0 = g_projh + ((size_t)b * HWN + p) * OC + nh * 128 + o0w + col2;
            #pragma unroll
            for (int nt = 0; nt < 4; nt++) {
                __half2 v0 = __floats2half2_rn(acc[i][nt][0] + biasv[nt].x,
                                               acc[i][nt][1] + biasv[nt].y);
                __half2 v1 = __floats2half2_rn(acc[i][nt][2] + biasv[nt].x,
                                               acc[i][nt][3] + biasv[nt].y);
                *(__half2*)(dst0 + nt * 8)          = v0;
                *(__half2*)(dst0 + nt * 8 + 8 * OC) = v1;
            }
        }
    }
}

// ---------------------------------------------------------------------------
// Kernel 3: out[b][o][p] = sum_{i<cnt} w_i * projh[b][idx_i][o]
// Round-4 lane layout (64 lanes x uint2, 4 pixels in flight) + cnt-bounded
// unconditional gather loop (unrolled x2; flow pads cnt to even).
__global__ __launch_bounds__(256) void DFMAtt_sample(float* __restrict__ out) {
    __shared__ float s_acc[32][257];
    __shared__ int   s_idx[32][16];
    __shared__ float s_wt [32][16];
    __shared__ int   s_cnt[32];

    int b  = blockIdx.y;
    int p0 = blockIdx.x * 32;
    int tid = threadIdx.x;

    {
        const int*   gi = g_sidx + (b * HWN + p0) * 16;
        const float* gw = g_swt  + (b * HWN + p0) * 16;
        for (int i = tid; i < 512; i += 256) {
            s_idx[i >> 4][i & 15] = gi[i];
            s_wt [i >> 4][i & 15] = gw[i];
        }
        if (tid < 32) s_cnt[tid] = g_scnt[b * HWN + p0 + tid];
    }
    __syncthreads();

    const __half* projb = g_projh + (size_t)b * HWN * OC;
    int lane = tid & 63;            // 64 lanes x 4 halves = 256 channels
    int psub = tid >> 6;            // 4 pixels in flight

    #pragma unroll 1
    for (int s = 0; s < 8; s++) {
        int pi = s * 4 + psub;      // uniform within warp
        int cnt = s_cnt[pi];
        const __half* pb = projb + lane * 4;
        float ax = 0.f, ay = 0.f, az = 0.f, aw = 0.f;
        #pragma unroll 1
        for (int i = 0; i < cnt; i += 2) {
            float w0 = s_wt[pi][i];
            float w1 = s_wt[pi][i + 1];
            uint2 r0 = *(const uint2*)(pb + s_idx[pi][i]);
            uint2 r1 = *(const uint2*)(pb + s_idx[pi][i + 1]);
            float2 a0 = __half22float2(*(__half2*)&r0.x);
            float2 a1 = __half22float2(*(__half2*)&r0.y);
            float2 b0 = __half22float2(*(__half2*)&r1.x);
            float2 b1 = __half22float2(*(__half2*)&r1.y);
            ax = fmaf(w0, a0.x, ax); ay = fmaf(w0, a0.y, ay);
            az = fmaf(w0, a1.x, az); aw = fmaf(w0, a1.y, aw);
            ax = fmaf(w1, b0.x, ax); ay = fmaf(w1, b0.y, ay);
            az = fmaf(w1, b1.x, az); aw = fmaf(w1, b1.y, aw);
        }
        float* sa = &s_acc[pi][lane * 4];
        sa[0] = ax; sa[1] = ay; sa[2] = az; sa[3] = aw;
    }
    __syncthreads();

    float* ob = out + (size_t)b * OC * HWN + p0;
    int orow = tid >> 5;
    int pi   = tid & 31;
    #pragma unroll 1
    for (int j = 0; j < 32; j++) {
        int o = orow + j * 8;
        ob[(size_t)o * HWN + pi] = s_acc[pi][o];
    }
}

// ---------------------------------------------------------------------------
extern "C" void kernel_launch(void* const* d_in, const int* in_sizes, int n_in,
                              void* d_out, int out_size) {
    const float* x    = (const float*)d_in[0];
    const float* Wc   = (const float*)d_in[1];
    const float* bc   = (const float*)d_in[2];
    const float* Woff = (const float*)d_in[3];
    const float* boff = (const float*)d_in[4];
    const float* Wwt  = (const float*)d_in[5];
    const float* bwt  = (const float*)d_in[6];
    float* out = (float*)d_out;

    cudaFuncSetAttribute(DFMAtt_gemm_mma,
                         cudaFuncAttributeMaxDynamicSharedMemorySize, SMEM_TOT);

    DFMAtt_wprep<<<OC, 256>>>(Wc);

    dim3 gf(HWN / 128, BB);
    DFMAtt_flow<<<gf, 128>>>(x, Woff, boff, Wwt, bwt);

    DFMAtt_gemm_mma<<<296, 256, SMEM_TOT>>>(bc);

    dim3 gs(HWN / 32, BB);
    DFMAtt_sample<<<gs, 256>>>(out);
}

// round 7
// speedup vs baseline: 2.5215x; 1.1354x over previous
#include <cuda_runtime.h>
#include <cuda_fp16.h>
#include <math.h>
#include <stdint.h>

#define BB   8
#define CCH  256
#define HH   96
#define WW   96
#define HWN  (HH*WW)        // 9216
#define OC   256
#define KF   4

// Scratch
__device__ __half g_projh[(size_t)BB * HWN * OC];        // [b][p][o] pixel-major, fp16
__device__ int    g_sidx[BB * HWN * 16];                 // compacted gather offsets
__device__ float  g_swt [BB * HWN * 16];                 // compacted fused weights
__device__ int    g_scnt[BB * HWN];                      // per-pixel tap count (even)
__device__ __half g_wh[OC * CCH];                        // fp16(Wc) [o][c]
__device__ __half g_xh[(size_t)BB * CCH * HWN];          // fp16(x) [b][c][p]

// ---------------------------------------------------------------------------
union P2 { float2 f; unsigned long long u; };
__device__ __forceinline__ void fma2(unsigned long long& d,
                                     unsigned long long a,
                                     unsigned long long b) {
    asm("fma.rn.f32x2 %0, %1, %2, %0;" : "+l"(d) : "l"(a), "l"(b));
}

__device__ __forceinline__ uint32_t smem_u32(const void* p) {
    uint32_t a;
    asm("{ .reg .u64 t; cvta.to.shared.u64 t, %1; cvt.u32.u64 %0, t; }" : "=r"(a) : "l"(p));
    return a;
}
#define CPA16(dst, src) asm volatile("cp.async.cg.shared.global [%0], [%1], 16;" :: "r"(dst), "l"(src) : "memory")
#define CPA_COMMIT()    asm volatile("cp.async.commit_group;" ::: "memory")
#define CPA_WAIT1()     asm volatile("cp.async.wait_group 1;" ::: "memory")

#define LDSM_X4(r, a) \
    asm volatile("ldmatrix.sync.aligned.m8n8.x4.shared.b16 {%0,%1,%2,%3}, [%4];" \
        : "=r"((r)[0]), "=r"((r)[1]), "=r"((r)[2]), "=r"((r)[3]) : "r"(a))
#define LDSM_X4_T(r, a) \
    asm volatile("ldmatrix.sync.aligned.m8n8.x4.trans.shared.b16 {%0,%1,%2,%3}, [%4];" \
        : "=r"((r)[0]), "=r"((r)[1]), "=r"((r)[2]), "=r"((r)[3]) : "r"(a))

__device__ __forceinline__ void mma16816(float* c, const uint32_t* a, const uint32_t* b) {
    asm volatile("mma.sync.aligned.m16n8k16.row.col.f32.f16.f16.f32 "
                 "{%0,%1,%2,%3}, {%4,%5,%6,%7}, {%8,%9}, {%0,%1,%2,%3};"
                 : "+f"(c[0]), "+f"(c[1]), "+f"(c[2]), "+f"(c[3])
                 : "r"(a[0]), "r"(a[1]), "r"(a[2]), "r"(a[3]), "r"(b[0]), "r"(b[1]));
}

// ---------------------------------------------------------------------------
// Kernel 0: Wc -> fp16
__global__ void DFMAtt_wprep(const float* __restrict__ Wc) {
    int i = blockIdx.x * 256 + threadIdx.x;
    g_wh[i] = __float2half_rn(Wc[i]);
}

// ---------------------------------------------------------------------------
// Kernel 1 (fused): flows + softmax -> dedupe -> compacted (idx, wt, cnt),
// AND fp16 conversion of x into g_xh.  Dot products via packed f32x2 FMA.
__global__ __launch_bounds__(128) void DFMAtt_flow(
        const float* __restrict__ x,
        const float* __restrict__ Woff, const float* __restrict__ boff,
        const float* __restrict__ Wwt,  const float* __restrict__ bwt) {
    __shared__ float2 sW2[12][CCH / 2];   // packed (c even, c odd) pairs
    int tid = threadIdx.x;
    for (int i = tid; i < 12 * (CCH / 2); i += 128) {
        int m = i >> 7, cc = i & 127;
        const float* src = (m < 8) ? (Woff + m * CCH) : (Wwt + (m - 8) * CCH);
        sW2[m][cc] = *(const float2*)(src + cc * 2);
    }
    __syncthreads();

    int b = blockIdx.y;
    int p = blockIdx.x * 128 + tid;
    const float* xp = x + (size_t)b * CCH * HWN + p;
    __half* xh = g_xh + (size_t)b * CCH * HWN + p;

    unsigned long long acc2[12];
    #pragma unroll
    for (int m = 0; m < 12; m++) acc2[m] = 0ull;

    #pragma unroll 4
    for (int c2 = 0; c2 < CCH / 2; c2++) {
        float xv0 = xp[(size_t)(c2 * 2)     * HWN];
        float xv1 = xp[(size_t)(c2 * 2 + 1) * HWN];
        xh[(size_t)(c2 * 2)     * HWN] = __float2half_rn(xv0);
        xh[(size_t)(c2 * 2 + 1) * HWN] = __float2half_rn(xv1);
        P2 xv; xv.f = make_float2(xv0, xv1);
        #pragma unroll
        for (int m = 0; m < 12; m++) {
            P2 w; w.f = sW2[m][c2];
            fma2(acc2[m], xv.u, w.u);
        }
    }
    float acc[12];
    #pragma unroll
    for (int m = 0; m < 12; m++) {
        P2 t; t.u = acc2[m];
        acc[m] = t.f.x + t.f.y;
    }

    float lg[KF];
    #pragma unroll
    for (int k = 0; k < KF; k++) lg[k] = acc[8 + k] + bwt[k];
    float mx = fmaxf(fmaxf(lg[0], lg[1]), fmaxf(lg[2], lg[3]));
    float e[KF], ssum = 0.f;
    #pragma unroll
    for (int k = 0; k < KF; k++) { e[k] = expf(lg[k] - mx); ssum += e[k]; }
    float inv = 1.f / ssum;

    int px = p % WW, py = p / WW;

    int   idxr[16];
    float wtr [16];
    bool  keep[16];
    #pragma unroll
    for (int k = 0; k < KF; k++) {
        float wk = e[k] * inv;
        float fx = acc[k * 2 + 0] + boff[k * 2 + 0];
        float fy = acc[k * 2 + 1] + boff[k * 2 + 1];
        float vx = 2.0f * ((float)px + fx) / (float)(WW - 1) - 1.0f;
        float vy = 2.0f * ((float)py + fy) / (float)(HH - 1) - 1.0f;
        float ix = (vx + 1.0f) * ((float)WW * 0.5f) - 0.5f;
        float iy = (vy + 1.0f) * ((float)HH * 0.5f) - 0.5f;
        float x0f = floorf(ix), y0f = floorf(iy);
        float wx1 = ix - x0f, wx0 = 1.0f - wx1;
        float wy1 = iy - y0f, wy0 = 1.0f - wy1;
        int x0 = (int)x0f, y0 = (int)y0f;
        #pragma unroll
        for (int t = 0; t < 4; t++) {
            int xi = x0 + (t & 1);
            int yi = y0 + (t >> 1);
            float wt = ((t & 1) ? wx1 : wx0) * ((t >> 1) ? wy1 : wy0);
            bool valid = (xi >= 0) && (xi < WW) && (yi >= 0) && (yi < HH);
            int xc = min(max(xi, 0), WW - 1);
            int yc = min(max(yi, 0), HH - 1);
            int q = k * 4 + t;
            idxr[q] = (yc * WW + xc) * OC;
            wtr [q] = valid ? (wk * wt) : 0.0f;
            keep[q] = true;
        }
    }

    #pragma unroll
    for (int j = 1; j < 16; j++)
        #pragma unroll
        for (int i = 0; i < j; i++)
            if (keep[j] && keep[i] && idxr[j] == idxr[i]) {
                wtr[i] += wtr[j];
                keep[j] = false;
            }

    int base = (b * HWN + p) * 16;
    int cnt = 0;
    #pragma unroll
    for (int t = 0; t < 16; t++)
        if (keep[t] && wtr[t] != 0.0f) {
            g_sidx[base + cnt] = idxr[t];
            g_swt [base + cnt] = wtr[t];
            cnt++;
        }
    if (cnt & 1) {
        g_sidx[base + cnt] = 0;
        g_swt [base + cnt] = 0.0f;
        cnt++;
    }
    g_scnt[b * HWN + p] = cnt;
}

// ---------------------------------------------------------------------------
// Kernel 2: mma.sync fp16 single-pass GEMM, 3-stage cp.async ring,
// ONE __syncthreads per k-chunk. Persistent 296 CTAs (2/SM).
#define BS_STRIDE 264
#define AS_STRIDE 136
#define B_MAT_BYTES (128 * BS_STRIDE * 2)   // 67584
#define A_STG_BYTES (32 * AS_STRIDE * 2)    // 8704
#define OFF_A B_MAT_BYTES
#define SMEM_TOT (OFF_A + 3 * A_STG_BYTES)  // 93696 -> 2 CTAs/SM

__device__ __forceinline__ void prefA(uint32_t smA, int st, int b, int ck, int prow, int tid) {
    #pragma unroll
    for (int it = 0; it < 2; it++) {
        int idx = tid + it * 256;
        int r = idx >> 4, j = idx & 15;
        const __half* src = g_xh + ((size_t)(b * CCH + ck * 32 + r)) * HWN + prow + j * 8;
        uint32_t dst = smA + (uint32_t)st * A_STG_BYTES + r * (AS_STRIDE * 2) + j * 16;
        CPA16(dst, src);
    }
}

__global__ __launch_bounds__(256, 2) void DFMAtt_gemm_mma(const float* __restrict__ bc) {
    extern __shared__ unsigned char sm[];
    uint32_t sb = smem_u32(sm);
    int tid = threadIdx.x, wid = tid >> 5, lane = tid & 31;
    int nh = (blockIdx.x >= 148) ? 1 : 0;
    int local = blockIdx.x % 148;

    for (int idx = tid; idx < 128 * 32; idx += 256) {
        int r = idx >> 5, j = idx & 31;
        const __half* wsrc = g_wh + (size_t)(nh * 128 + r) * CCH + j * 8;
        *(uint4*)(sm + r * (BS_STRIDE * 2) + j * 16) = *(const uint4*)wsrc;
    }

    int wm = wid >> 2, wn = wid & 3;
    int p0w = wm * 64, o0w = wn * 32;
    int grp = lane >> 3, lr = lane & 7;

    int a_dc = ((grp >> 1) << 3) + lr;
    int a_dp = (grp & 1) << 3;
    uint32_t aoff[4];
    #pragma unroll
    for (int i = 0; i < 4; i++)
        aoff[i] = (uint32_t)(a_dc * (AS_STRIDE * 2) + (p0w + i * 16 + a_dp) * 2);
    int b_dr = ((grp >> 1) << 3) + lr;
    int b_dk = (grp & 1) << 4;
    uint32_t boff[2];
    #pragma unroll
    for (int t = 0; t < 2; t++)
        boff[t] = (uint32_t)((o0w + t * 16 + b_dr) * (BS_STRIDE * 2) + b_dk);

    uint32_t smA = sb + OFF_A;

    int row = lane >> 2, col2 = (lane & 3) * 2;
    float2 biasv[4];
    #pragma unroll
    for (int nt = 0; nt < 4; nt++)
        biasv[nt] = *(const float2*)&bc[nh * 128 + o0w + nt * 8 + col2];

    for (int mt = local; mt < 576; mt += 148) {
        int b = mt / 72, prow = (mt % 72) * 128;

        float acc[4][4][4];
        #pragma unroll
        for (int i = 0; i < 4; i++)
            #pragma unroll
            for (int nt = 0; nt < 4; nt++)
                #pragma unroll
                for (int q = 0; q < 4; q++) acc[i][nt][q] = 0.f;

        __syncthreads();   // prior tile's (or B-load's) smem reads complete
        prefA(smA, 0, b, 0, prow, tid); CPA_COMMIT();
        prefA(smA, 1, b, 1, prow, tid); CPA_COMMIT();

        #pragma unroll 1
        for (int ck = 0; ck < 8; ck++) {
            CPA_WAIT1();
            __syncthreads();            // single barrier per chunk
            int st = ck % 3;
            uint32_t Ab = smA + (uint32_t)st * A_STG_BYTES;

            #pragma unroll
            for (int ks = 0; ks < 2; ks++) {
                uint32_t ac  = (uint32_t)(ks * 16 * (AS_STRIDE * 2));
                uint32_t bcf = (uint32_t)((ck * 32 + ks * 16) * 2);
                uint32_t ah[4][4];
                #pragma unroll
                for (int i = 0; i < 4; i++) LDSM_X4_T(ah[i], Ab + ac + aoff[i]);
                uint32_t bh[2][4];
                #pragma unroll
                for (int t = 0; t < 2; t++) LDSM_X4(bh[t], sb + bcf + boff[t]);
                #pragma unroll
                for (int i = 0; i < 4; i++)
                    #pragma unroll
                    for (int nt = 0; nt < 4; nt++)
                        mma16816(acc[i][nt], ah[i], &bh[nt >> 1][(nt & 1) * 2]);
            }

            int nck = ck + 2;           // prefetch into stage (ck+2)%3 = (ck-1)%3,
            if (nck < 8)                // whose readers finished before this barrier
                prefA(smA, nck % 3, b, nck, prow, tid);
            CPA_COMMIT();
        }

        #pragma unroll
        for (int i = 0; i < 4; i++) {
            int p = prow + p0w + i * 16 + row;
            __half* dst0 = g_projh + ((size_t)b * HWN + p) * OC + nh * 128 + o0w + col2;
            #pragma unroll
            for (int nt = 0; nt < 4; nt++) {
                __half2 v0 = __floats2half2_rn(acc[i][nt][0] + biasv[nt].x,
                                               acc[i][nt][1] + biasv[nt].y);
                __half2 v1 = __floats2half2_rn(acc[i][nt][2] + biasv[nt].x,
                                               acc[i][nt][3] + biasv[nt].y);
                *(__half2*)(dst0 + nt * 8)          = v0;
                *(__half2*)(dst0 + nt * 8 + 8 * OC) = v1;
            }
        }
    }
}

// ---------------------------------------------------------------------------
// Kernel 3: out[b][o][p] = sum_{i<cnt} w_i * projh[b][idx_i][o]
__global__ __launch_bounds__(256) void DFMAtt_sample(float* __restrict__ out) {
    __shared__ float s_acc[32][257];
    __shared__ int   s_idx[32][16];
    __shared__ float s_wt [32][16];
    __shared__ int   s_cnt[32];

    int b  = blockIdx.y;
    int p0 = blockIdx.x * 32;
    int tid = threadIdx.x;

    {
        const int*   gi = g_sidx + (b * HWN + p0) * 16;
        const float* gw = g_swt  + (b * HWN + p0) * 16;
        for (int i = tid; i < 512; i += 256) {
            s_idx[i >> 4][i & 15] = gi[i];
            s_wt [i >> 4][i & 15] = gw[i];
        }
        if (tid < 32) s_cnt[tid] = g_scnt[b * HWN + p0 + tid];
    }
    __syncthreads();

    const __half* projb = g_projh + (size_t)b * HWN * OC;
    int lane = tid & 63;
    int psub = tid >> 6;

    #pragma unroll 1
    for (int s = 0; s < 8; s++) {
        int pi = s * 4 + psub;
        int cnt = s_cnt[pi];
        const __half* pb = projb + lane * 4;
        float ax = 0.f, ay = 0.f, az = 0.f, aw = 0.f;
        #pragma unroll 1
        for (int i = 0; i < cnt; i += 2) {
            float w0 = s_wt[pi][i];
            float w1 = s_wt[pi][i + 1];
            uint2 r0 = *(const uint2*)(pb + s_idx[pi][i]);
            uint2 r1 = *(const uint2*)(pb + s_idx[pi][i + 1]);
            float2 a0 = __half22float2(*(__half2*)&r0.x);
            float2 a1 = __half22float2(*(__half2*)&r0.y);
            float2 b0 = __half22float2(*(__half2*)&r1.x);
            float2 b1 = __half22float2(*(__half2*)&r1.y);
            ax = fmaf(w0, a0.x, ax); ay = fmaf(w0, a0.y, ay);
            az = fmaf(w0, a1.x, az); aw = fmaf(w0, a1.y, aw);
            ax = fmaf(w1, b0.x, ax); ay = fmaf(w1, b0.y, ay);
            az = fmaf(w1, b1.x, az); aw = fmaf(w1, b1.y, aw);
        }
        float* sa = &s_acc[pi][lane * 4];
        sa[0] = ax; sa[1] = ay; sa[2] = az; sa[3] = aw;
    }
    __syncthreads();

    float* ob = out + (size_t)b * OC * HWN + p0;
    int orow = tid >> 5;
    int pi   = tid & 31;
    #pragma unroll 1
    for (int j = 0; j < 32; j++) {
        int o = orow + j * 8;
        ob[(size_t)o * HWN + pi] = s_acc[pi][o];
    }
}

// ---------------------------------------------------------------------------
extern "C" void kernel_launch(void* const* d_in, const int* in_sizes, int n_in,
                              void* d_out, int out_size) {
    const float* x    = (const float*)d_in[0];
    const float* Wc   = (const float*)d_in[1];
    const float* bc   = (const float*)d_in[2];
    const float* Woff = (const float*)d_in[3];
    const float* boff = (const float*)d_in[4];
    const float* Wwt  = (const float*)d_in[5];
    const float* bwt  = (const float*)d_in[6];
    float* out = (float*)d_out;

    cudaFuncSetAttribute(DFMAtt_gemm_mma,
                         cudaFuncAttributeMaxDynamicSharedMemorySize, SMEM_TOT);

    DFMAtt_wprep<<<OC, 256>>>(Wc);

    dim3 gf(HWN / 128, BB);
    DFMAtt_flow<<<gf, 128>>>(x, Woff, boff, Wwt, bwt);

    DFMAtt_gemm_mma<<<296, 256, SMEM_TOT>>>(bc);

    dim3 gs(HWN / 32, BB);
    DFMAtt_sample<<<gs, 256>>>(out);
}

// round 10
// speedup vs baseline: 2.5221x; 1.0002x over previous
#include <cuda_runtime.h>
#include <cuda_fp16.h>
#include <math.h>
#include <stdint.h>

#define BB   8
#define CCH  256
#define HH   96
#define WW   96
#define HWN  (HH*WW)        // 9216
#define OC   256
#define KF   4

// Scratch
__device__ __half g_projh[(size_t)BB * HWN * OC];        // [b][p][o] pixel-major, fp16
__device__ int    g_sidx[BB * HWN * 16];                 // compacted gather offsets
__device__ float  g_swt [BB * HWN * 16];                 // compacted fused weights
__device__ int    g_scnt[BB * HWN];                      // per-pixel tap count (even)
__device__ __half g_wh[OC * CCH];                        // fp16(Wc) [o][c]
__device__ __half g_xh[(size_t)BB * CCH * HWN];          // fp16(x) [b][c][p]

// ---------------------------------------------------------------------------
union P2 { float2 f; unsigned long long u; };
__device__ __forceinline__ void fma2(unsigned long long& d,
                                     unsigned long long a,
                                     unsigned long long b) {
    asm("fma.rn.f32x2 %0, %1, %2, %0;" : "+l"(d) : "l"(a), "l"(b));
}

__device__ __forceinline__ uint32_t smem_u32(const void* p) {
    uint32_t a;
    asm("{ .reg .u64 t; cvta.to.shared.u64 t, %1; cvt.u32.u64 %0, t; }" : "=r"(a) : "l"(p));
    return a;
}
#define CPA16(dst, src) asm volatile("cp.async.cg.shared.global [%0], [%1], 16;" :: "r"(dst), "l"(src) : "memory")
#define CPA_COMMIT()    asm volatile("cp.async.commit_group;" ::: "memory")
#define CPA_WAIT1()     asm volatile("cp.async.wait_group 1;" ::: "memory")

#define LDSM_X4(r, a) \
    asm volatile("ldmatrix.sync.aligned.m8n8.x4.shared.b16 {%0,%1,%2,%3}, [%4];" \
        : "=r"((r)[0]), "=r"((r)[1]), "=r"((r)[2]), "=r"((r)[3]) : "r"(a))
#define LDSM_X4_T(r, a) \
    asm volatile("ldmatrix.sync.aligned.m8n8.x4.trans.shared.b16 {%0,%1,%2,%3}, [%4];" \
        : "=r"((r)[0]), "=r"((r)[1]), "=r"((r)[2]), "=r"((r)[3]) : "r"(a))

__device__ __forceinline__ void mma16816(float* c, const uint32_t* a, const uint32_t* b) {
    asm volatile("mma.sync.aligned.m16n8k16.row.col.f32.f16.f16.f32 "
                 "{%0,%1,%2,%3}, {%4,%5,%6,%7}, {%8,%9}, {%0,%1,%2,%3};"
                 : "+f"(c[0]), "+f"(c[1]), "+f"(c[2]), "+f"(c[3])
                 : "r"(a[0]), "r"(a[1]), "r"(a[2]), "r"(a[3]), "r"(b[0]), "r"(b[1]));
}

// ---------------------------------------------------------------------------
// Kernel 1 (fused): flows + softmax -> dedupe -> compacted (idx, wt, cnt),
// fp16 conversion of x into g_xh, AND Wc->fp16 (spread over first 512 blocks).
__global__ __launch_bounds__(128) void DFMAtt_flow(
        const float* __restrict__ x,   const float* __restrict__ Wc,
        const float* __restrict__ Woff, const float* __restrict__ boff,
        const float* __restrict__ Wwt,  const float* __restrict__ bwt) {
    __shared__ float2 sW2[12][CCH / 2];
    int tid = threadIdx.x;

    // folded wprep: 512 of 576 blocks convert 128 Wc elements each
    {
        int blk = blockIdx.y * 72 + blockIdx.x;
        if (blk < 512) {
            int i = blk * 128 + tid;
            g_wh[i] = __float2half_rn(Wc[i]);
        }
    }

    for (int i = tid; i < 12 * (CCH / 2); i += 128) {
        int m = i >> 7, cc = i & 127;
        const float* src = (m < 8) ? (Woff + m * CCH) : (Wwt + (m - 8) * CCH);
        sW2[m][cc] = *(const float2*)(src + cc * 2);
    }
    __syncthreads();

    int b = blockIdx.y;
    int p = blockIdx.x * 128 + tid;
    const float* xp = x + (size_t)b * CCH * HWN + p;
    __half* xh = g_xh + (size_t)b * CCH * HWN + p;

    unsigned long long acc2[12];
    #pragma unroll
    for (int m = 0; m < 12; m++) acc2[m] = 0ull;

    #pragma unroll 4
    for (int c2 = 0; c2 < CCH / 2; c2++) {
        float xv0 = xp[(size_t)(c2 * 2)     * HWN];
        float xv1 = xp[(size_t)(c2 * 2 + 1) * HWN];
        xh[(size_t)(c2 * 2)     * HWN] = __float2half_rn(xv0);
        xh[(size_t)(c2 * 2 + 1) * HWN] = __float2half_rn(xv1);
        P2 xv; xv.f = make_float2(xv0, xv1);
        #pragma unroll
        for (int m = 0; m < 12; m++) {
            P2 w; w.f = sW2[m][c2];
            fma2(acc2[m], xv.u, w.u);
        }
    }
    float acc[12];
    #pragma unroll
    for (int m = 0; m < 12; m++) {
        P2 t; t.u = acc2[m];
        acc[m] = t.f.x + t.f.y;
    }

    float lg[KF];
    #pragma unroll
    for (int k = 0; k < KF; k++) lg[k] = acc[8 + k] + bwt[k];
    float mx = fmaxf(fmaxf(lg[0], lg[1]), fmaxf(lg[2], lg[3]));
    float e[KF], ssum = 0.f;
    #pragma unroll
    for (int k = 0; k < KF; k++) { e[k] = expf(lg[k] - mx); ssum += e[k]; }
    float inv = 1.f / ssum;

    int px = p % WW, py = p / WW;

    int   idxr[16];
    float wtr [16];
    bool  keep[16];
    #pragma unroll
    for (int k = 0; k < KF; k++) {
        float wk = e[k] * inv;
        float fx = acc[k * 2 + 0] + boff[k * 2 + 0];
        float fy = acc[k * 2 + 1] + boff[k * 2 + 1];
        float vx = 2.0f * ((float)px + fx) / (float)(WW - 1) - 1.0f;
        float vy = 2.0f * ((float)py + fy) / (float)(HH - 1) - 1.0f;
        float ix = (vx + 1.0f) * ((float)WW * 0.5f) - 0.5f;
        float iy = (vy + 1.0f) * ((float)HH * 0.5f) - 0.5f;
        float x0f = floorf(ix), y0f = floorf(iy);
        float wx1 = ix - x0f, wx0 = 1.0f - wx1;
        float wy1 = iy - y0f, wy0 = 1.0f - wy1;
        int x0 = (int)x0f, y0 = (int)y0f;
        #pragma unroll
        for (int t = 0; t < 4; t++) {
            int xi = x0 + (t & 1);
            int yi = y0 + (t >> 1);
            float wt = ((t & 1) ? wx1 : wx0) * ((t >> 1) ? wy1 : wy0);
            bool valid = (xi >= 0) && (xi < WW) && (yi >= 0) && (yi < HH);
            int xc = min(max(xi, 0), WW - 1);
            int yc = min(max(yi, 0), HH - 1);
            int q = k * 4 + t;
            idxr[q] = (yc * WW + xc) * OC;
            wtr [q] = valid ? (wk * wt) : 0.0f;
            keep[q] = true;
        }
    }

    #pragma unroll
    for (int j = 1; j < 16; j++)
        #pragma unroll
        for (int i = 0; i < j; i++)
            if (keep[j] && keep[i] && idxr[j] == idxr[i]) {
                wtr[i] += wtr[j];
                keep[j] = false;
            }

    int base = (b * HWN + p) * 16;
    int cnt = 0;
    #pragma unroll
    for (int t = 0; t < 16; t++)
        if (keep[t] && wtr[t] != 0.0f) {
            g_sidx[base + cnt] = idxr[t];
            g_swt [base + cnt] = wtr[t];
            cnt++;
        }
    if (cnt & 1) {
        g_sidx[base + cnt] = 0;
        g_swt [base + cnt] = 0.0f;
        cnt++;
    }
    g_scnt[b * HWN + p] = cnt;
}

// ---------------------------------------------------------------------------
// Kernel 2: mma.sync fp16 GEMM, CONTINUOUS 3-stage cp.async ring spanning
// tile boundaries (no tile-start barrier; epilogue overlaps next tile's
// loads). Persistent 296 CTAs (2/SM).
#define BS_STRIDE 264
#define AS_STRIDE 136
#define B_MAT_BYTES (128 * BS_STRIDE * 2)   // 67584
#define A_STG_BYTES (32 * AS_STRIDE * 2)    // 8704
#define OFF_A B_MAT_BYTES
#define SMEM_TOT (OFF_A + 3 * A_STG_BYTES)  // 93696 -> 2 CTAs/SM

__device__ __forceinline__ void prefA(uint32_t smA, int st, int b, int ck, int prow, int tid) {
    #pragma unroll
    for (int it = 0; it < 2; it++) {
        int idx = tid + it * 256;
        int r = idx >> 4, j = idx & 15;
        const __half* src = g_xh + ((size_t)(b * CCH + ck * 32 + r)) * HWN + prow + j * 8;
        uint32_t dst = smA + (uint32_t)st * A_STG_BYTES + r * (AS_STRIDE * 2) + j * 16;
        CPA16(dst, src);
    }
}

__global__ __launch_bounds__(256, 2) void DFMAtt_gemm_mma(const float* __restrict__ bc) {
    extern __shared__ unsigned char sm[];
    uint32_t sb = smem_u32(sm);
    int tid = threadIdx.x, wid = tid >> 5, lane = tid & 31;
    int nh = (blockIdx.x >= 148) ? 1 : 0;
    int local = blockIdx.x % 148;

    for (int idx = tid; idx < 128 * 32; idx += 256) {
        int r = idx >> 5, j = idx & 31;
        const __half* wsrc = g_wh + (size_t)(nh * 128 + r) * CCH + j * 8;
        *(uint4*)(sm + r * (BS_STRIDE * 2) + j * 16) = *(const uint4*)wsrc;
    }

    int wm = wid >> 2, wn = wid & 3;
    int p0w = wm * 64, o0w = wn * 32;
    int grp = lane >> 3, lr = lane & 7;

    int a_dc = ((grp >> 1) << 3) + lr;
    int a_dp = (grp & 1) << 3;
    uint32_t aoff[4];
    #pragma unroll
    for (int i = 0; i < 4; i++)
        aoff[i] = (uint32_t)(a_dc * (AS_STRIDE * 2) + (p0w + i * 16 + a_dp) * 2);
    int b_dr = ((grp >> 1) << 3) + lr;
    int b_dk = (grp & 1) << 4;
    uint32_t boff[2];
    #pragma unroll
    for (int t = 0; t < 2; t++)
        boff[t] = (uint32_t)((o0w + t * 16 + b_dr) * (BS_STRIDE * 2) + b_dk);

    uint32_t smA = sb + OFF_A;

    int row = lane >> 2, col2 = (lane & 3) * 2;
    float2 biasv[4];
    #pragma unroll
    for (int nt = 0; nt < 4; nt++)
        biasv[nt] = *(const float2*)&bc[nh * 128 + o0w + nt * 8 + col2];

    int T = (576 - local + 147) / 148;      // tiles for this CTA (3 or 4)
    int bb = local / 72, pr = local % 72;   // current tile (b, prow/128)

    // prime the ring: chunks 0,1 of first tile
    prefA(smA, 0, bb, 0, pr * 128, tid); CPA_COMMIT();
    prefA(smA, 1, bb, 1, pr * 128, tid); CPA_COMMIT();

    int g = 0;
    for (int ti = 0; ti < T; ti++) {
        int b = bb, prow = pr * 128;
        // next tile coords (mt += 148 = 2*72 + 4)
        int bbN = bb + 2, prN = pr + 4;
        if (prN >= 72) { prN -= 72; bbN++; }

        float acc[4][4][4];
        #pragma unroll
        for (int i = 0; i < 4; i++)
            #pragma unroll
            for (int nt = 0; nt < 4; nt++)
                #pragma unroll
                for (int q = 0; q < 4; q++) acc[i][nt][q] = 0.f;

        #pragma unroll 1
        for (int ck = 0; ck < 8; ck++, g++) {
            CPA_WAIT1();
            __syncthreads();            // single barrier per chunk
            uint32_t Ab = smA + (uint32_t)(g % 3) * A_STG_BYTES;

            #pragma unroll
            for (int ks = 0; ks < 2; ks++) {
                uint32_t ac  = (uint32_t)(ks * 16 * (AS_STRIDE * 2));
                uint32_t bcf = (uint32_t)((ck * 32 + ks * 16) * 2);
                uint32_t ah[4][4];
                #pragma unroll
                for (int i = 0; i < 4; i++) LDSM_X4_T(ah[i], Ab + ac + aoff[i]);
                uint32_t bh[2][4];
                #pragma unroll
                for (int t = 0; t < 2; t++) LDSM_X4(bh[t], sb + bcf + boff[t]);
                #pragma unroll
                for (int i = 0; i < 4; i++)
                    #pragma unroll
                    for (int nt = 0; nt < 4; nt++)
                        mma16816(acc[i][nt], ah[i], &bh[nt >> 1][(nt & 1) * 2]);
            }

            // prefetch chunk g+2 (possibly next tile's chunk ck-6)
            int gp = g + 2;
            if (gp < T * 8) {
                if (ck < 6) prefA(smA, gp % 3, b,   (ck + 2),     prow,      tid);
                else        prefA(smA, gp % 3, bbN, (ck + 2) & 7, prN * 128, tid);
            }
            CPA_COMMIT();
        }

        // epilogue overlaps next tile's in-flight cp.async (regs only)
        #pragma unroll
        for (int i = 0; i < 4; i++) {
            int p = prow + p0w + i * 16 + row;
            __half* dst0 = g_projh + ((size_t)b * HWN + p) * OC + nh * 128 + o0w + col2;
            #pragma unroll
            for (int nt = 0; nt < 4; nt++) {
                __half2 v0 = __floats2half2_rn(acc[i][nt][0] + biasv[nt].x,
                                               acc[i][nt][1] + biasv[nt].y);
                __half2 v1 = __floats2half2_rn(acc[i][nt][2] + biasv[nt].x,
                                               acc[i][nt][3] + biasv[nt].y);
                *(__half2*)(dst0 + nt * 8)          = v0;
                *(__half2*)(dst0 + nt * 8 + 8 * OC) = v1;
            }
        }
        bb = bbN; pr = prN;
    }
}

// ---------------------------------------------------------------------------
// Kernel 3: out[b][o][p] = sum_{i<cnt} w_i * projh[b][idx_i][o]
// 32 lanes x uint4 (one LDG.128 per tap per warp), 8 pixels in flight,
// unconditional cnt-bounded loop (unrolled x2).
__global__ __launch_bounds__(256) void DFMAtt_sample(float* __restrict__ out) {
    __shared__ float s_acc[32][257];
    __shared__ int   s_idx[32][16];
    __shared__ float s_wt [32][16];
    __shared__ int   s_cnt[32];

    int b  = blockIdx.y;
    int p0 = blockIdx.x * 32;
    int tid = threadIdx.x;

    {
        const int*   gi = g_sidx + (b * HWN + p0) * 16;
        const float* gw = g_swt  + (b * HWN + p0) * 16;
        for (int i = tid; i < 512; i += 256) {
            s_idx[i >> 4][i & 15] = gi[i];
            s_wt [i >> 4][i & 15] = gw[i];
        }
        if (tid < 32) s_cnt[tid] = g_scnt[b * HWN + p0 + tid];
    }
    __syncthreads();

    const __half* projb = g_projh + (size_t)b * HWN * OC;
    int lane = tid & 31;            // 32 lanes x 8 halves = 256 channels
    int pg   = tid >> 5;            // 8 pixels in flight

    #pragma unroll 1
    for (int s = 0; s < 4; s++) {
        int pi = s * 8 + pg;        // uniform within warp
        int cnt = s_cnt[pi];
        const __half* pb = projb + lane * 8;
        float f0 = 0.f, f1 = 0.f, f2 = 0.f, f3 = 0.f;
        float f4 = 0.f, f5 = 0.f, f6 = 0.f, f7 = 0.f;
        #pragma unroll 1
        for (int i = 0; i < cnt; i += 2) {
            float w0 = s_wt[pi][i];
            float w1 = s_wt[pi][i + 1];
            uint4 r0 = *(const uint4*)(pb + s_idx[pi][i]);
            uint4 r1 = *(const uint4*)(pb + s_idx[pi][i + 1]);
            float2 a0 = __half22float2(*(__half2*)&r0.x);
            float2 a1 = __half22float2(*(__half2*)&r0.y);
            float2 a2 = __half22float2(*(__half2*)&r0.z);
            float2 a3 = __half22float2(*(__half2*)&r0.w);
            f0 = fmaf(w0, a0.x, f0); f1 = fmaf(w0, a0.y, f1);
            f2 = fmaf(w0, a1.x, f2); f3 = fmaf(w0, a1.y, f3);
            f4 = fmaf(w0, a2.x, f4); f5 = fmaf(w0, a2.y, f5);
            f6 = fmaf(w0, a3.x, f6); f7 = fmaf(w0, a3.y, f7);
            float2 c0 = __half22float2(*(__half2*)&r1.x);
            float2 c1 = __half22float2(*(__half2*)&r1.y);
            float2 c2 = __half22float2(*(__half2*)&r1.z);
            float2 c3 = __half22float2(*(__half2*)&r1.w);
            f0 = fmaf(w1, c0.x, f0); f1 = fmaf(w1, c0.y, f1);
            f2 = fmaf(w1, c1.x, f2); f3 = fmaf(w1, c1.y, f3);
            f4 = fmaf(w1, c2.x, f4); f5 = fmaf(w1, c2.y, f5);
            f6 = fmaf(w1, c3.x, f6); f7 = fmaf(w1, c3.y, f7);
        }
        float* sa = &s_acc[pi][lane * 8];
        sa[0] = f0; sa[1] = f1; sa[2] = f2; sa[3] = f3;
        sa[4] = f4; sa[5] = f5; sa[6] = f6; sa[7] = f7;
    }
    __syncthreads();

    float* ob = out + (size_t)b * OC * HWN + p0;
    int orow = tid >> 5;
    int pi   = tid & 31;
    #pragma unroll 1
    for (int j = 0; j < 32; j++) {
        int o = orow + j * 8;
        ob[(size_t)o * HWN + pi] = s_acc[pi][o];
    }
}

// ---------------------------------------------------------------------------
extern "C" void kernel_launch(void* const* d_in, const int* in_sizes, int n_in,
                              void* d_out, int out_size) {
    const float* x    = (const float*)d_in[0];
    const float* Wc   = (const float*)d_in[1];
    const float* bc   = (const float*)d_in[2];
    const float* Woff = (const float*)d_in[3];
    const float* boff = (const float*)d_in[4];
    const float* Wwt  = (const float*)d_in[5];
    const float* bwt  = (const float*)d_in[6];
    float* out = (float*)d_out;

    cudaFuncSetAttribute(DFMAtt_gemm_mma,
                         cudaFuncAttributeMaxDynamicSharedMemorySize, SMEM_TOT);

    dim3 gf(HWN / 128, BB);
    DFMAtt_flow<<<gf, 128>>>(x, Wc, Woff, boff, Wwt, bwt);

    DFMAtt_gemm_mma<<<296, 256, SMEM_TOT>>>(bc);

    dim3 gs(HWN / 32, BB);
    DFMAtt_sample<<<gs, 256>>>(out);
}